// round 1
// baseline (speedup 1.0000x reference)
#include <cuda_runtime.h>

#define Ndim 8192
#define Hdim 1024
#define Kdim 4096

#define BM 128
#define BN 128
#define BK 16
#define TM 8
#define TN 8

// Static device scratch (no runtime allocation allowed).
__device__ float g_wn[(size_t)Kdim * Hdim];  // gathered weight[noise]  [K, H]
__device__ float g_bn[Kdim];                 // bias[noise]
__device__ float g_pn[Kdim];                 // unigram_prob[noise]

// ---------------------------------------------------------------------------
// Gather weight rows for the noise set into dense scratch. 4096 blocks x 256.
// ---------------------------------------------------------------------------
__global__ void gather_noise_kernel(const float* __restrict__ weight,
                                    const float* __restrict__ bias,
                                    const float* __restrict__ up,
                                    const int* __restrict__ noise) {
    int k = blockIdx.x;
    int v = noise[k];
    const float4* src = reinterpret_cast<const float4*>(weight + (size_t)v * Hdim);
    float4* dst = reinterpret_cast<float4*>(g_wn + (size_t)k * Hdim);
    dst[threadIdx.x] = src[threadIdx.x];   // 256 threads x float4 = 1024 floats
    if (threadIdx.x == 0) {
        g_bn[k] = bias[v];
        g_pn[k] = up[v];
    }
}

// ---------------------------------------------------------------------------
// pmt / pnt: one warp per row n; dot(input[n], weight[target[n]]) over H=1024.
// blockDim = (32, 8)  -> 8 rows per block; grid = N/8 blocks.
// ---------------------------------------------------------------------------
__global__ void target_kernel(const float* __restrict__ input,
                              const float* __restrict__ weight,
                              const float* __restrict__ bias,
                              const float* __restrict__ up,
                              const int* __restrict__ target,
                              float* __restrict__ out_pmt,
                              float* __restrict__ out_pnt) {
    int n = blockIdx.x * 8 + threadIdx.y;
    int lane = threadIdx.x;
    int t = target[n];
    const float4* a = reinterpret_cast<const float4*>(input + (size_t)n * Hdim);
    const float4* w = reinterpret_cast<const float4*>(weight + (size_t)t * Hdim);
    float s = 0.f;
#pragma unroll
    for (int j = 0; j < 8; j++) {
        float4 av = a[lane + j * 32];
        float4 wv = w[lane + j * 32];
        s += av.x * wv.x + av.y * wv.y + av.z * wv.z + av.w * wv.w;
    }
#pragma unroll
    for (int o = 16; o; o >>= 1) s += __shfl_xor_sync(0xffffffffu, s, o);
    if (lane == 0) {
        out_pmt[n] = expf(s + bias[t]);
        out_pnt[n] = up[t];
    }
}

// ---------------------------------------------------------------------------
// Main GEMM: pmn[n,k] = exp(input[n,:] . g_wn[k,:] + g_bn[k])
// Fused epilogue also writes pnn[n,k] = g_pn[k] (pure broadcast).
// 128x128 tile, BK=16, 8x8 per thread, 256 threads, fp32 accumulation.
// ---------------------------------------------------------------------------
__global__ __launch_bounds__(256, 2)
void nce_gemm_kernel(const float* __restrict__ A,
                     float* __restrict__ out_pmn,
                     float* __restrict__ out_pnn) {
    __shared__ float As[BK][BM];
    __shared__ float Bs[BK][BN];

    const int tid = threadIdx.x;
    const int tx = tid & 15;    // column group 0..15
    const int ty = tid >> 4;    // row group    0..15
    const int row0 = blockIdx.y * BM;
    const int col0 = blockIdx.x * BN;

    float acc[TM][TN];
#pragma unroll
    for (int i = 0; i < TM; i++)
#pragma unroll
        for (int j = 0; j < TN; j++) acc[i][j] = 0.f;

    // Tile-load mapping: 128 rows x 16 cols = 512 float4 loads; 2 per thread.
    const int lr  = tid >> 2;   // 0..63 (plus i*64)
    const int lc4 = tid & 3;    // float4 slot within a 16-float row

    for (int kk = 0; kk < Hdim; kk += BK) {
#pragma unroll
        for (int i = 0; i < 2; i++) {
            int r = lr + i * 64;
            float4 v = *reinterpret_cast<const float4*>(
                &A[(size_t)(row0 + r) * Hdim + kk + lc4 * 4]);
            As[lc4 * 4 + 0][r] = v.x;
            As[lc4 * 4 + 1][r] = v.y;
            As[lc4 * 4 + 2][r] = v.z;
            As[lc4 * 4 + 3][r] = v.w;
            float4 w = *reinterpret_cast<const float4*>(
                &g_wn[(size_t)(col0 + r) * Hdim + kk + lc4 * 4]);
            Bs[lc4 * 4 + 0][r] = w.x;
            Bs[lc4 * 4 + 1][r] = w.y;
            Bs[lc4 * 4 + 2][r] = w.z;
            Bs[lc4 * 4 + 3][r] = w.w;
        }
        __syncthreads();

#pragma unroll
        for (int k = 0; k < BK; k++) {
            float a[TM], b[TN];
#pragma unroll
            for (int i = 0; i < TM; i++) a[i] = As[k][ty * TM + i];
#pragma unroll
            for (int j = 0; j < TN; j++) b[j] = Bs[k][tx * TN + j];
#pragma unroll
            for (int i = 0; i < TM; i++)
#pragma unroll
                for (int j = 0; j < TN; j++)
                    acc[i][j] = fmaf(a[i], b[j], acc[i][j]);
        }
        __syncthreads();
    }

    // Epilogue: exp(acc + bias) -> pmn, broadcast unigram -> pnn.
    float bn[TN], pn[TN];
#pragma unroll
    for (int j = 0; j < TN; j++) {
        bn[j] = g_bn[col0 + tx * TN + j];
        pn[j] = g_pn[col0 + tx * TN + j];
    }
#pragma unroll
    for (int i = 0; i < TM; i++) {
        size_t base = (size_t)(row0 + ty * TM + i) * Kdim + col0 + tx * TN;
#pragma unroll
        for (int j = 0; j < TN; j += 4) {
            float4 e;
            e.x = expf(acc[i][j + 0] + bn[j + 0]);
            e.y = expf(acc[i][j + 1] + bn[j + 1]);
            e.z = expf(acc[i][j + 2] + bn[j + 2]);
            e.w = expf(acc[i][j + 3] + bn[j + 3]);
            *reinterpret_cast<float4*>(&out_pmn[base + j]) = e;
            float4 p;
            p.x = pn[j + 0]; p.y = pn[j + 1]; p.z = pn[j + 2]; p.w = pn[j + 3];
            *reinterpret_cast<float4*>(&out_pnn[base + j]) = p;
        }
    }
}

// ---------------------------------------------------------------------------
// Launch. Output layout (flattened tuple): pmt[N] | pnt[N] | pmn[N*K] | pnn[N*K]
// ---------------------------------------------------------------------------
extern "C" void kernel_launch(void* const* d_in, const int* in_sizes, int n_in,
                              void* d_out, int out_size) {
    const float* input  = (const float*)d_in[0];
    const float* weight = (const float*)d_in[1];
    const float* bias   = (const float*)d_in[2];
    const float* up     = (const float*)d_in[3];
    const int*   target = (const int*)d_in[4];
    const int*   noise  = (const int*)d_in[5];

    float* out     = (float*)d_out;
    float* out_pmt = out;
    float* out_pnt = out + Ndim;
    float* out_pmn = out + 2 * Ndim;
    float* out_pnn = out_pmn + (size_t)Ndim * Kdim;

    gather_noise_kernel<<<Kdim, 256>>>(weight, bias, up, noise);
    target_kernel<<<Ndim / 8, dim3(32, 8)>>>(input, weight, bias, up, target,
                                             out_pmt, out_pnt);
    dim3 grid(Kdim / BN, Ndim / BM);
    nce_gemm_kernel<<<grid, 256>>>(input, out_pmn, out_pnn);
}

// round 3
// speedup vs baseline: 3.0002x; 3.0002x over previous
#include <cuda_runtime.h>
#include <cuda_bf16.h>
#include <cstdint>

#define Mdim 8192          // output rows  (problem N)
#define Cdim 4096          // output cols  (problem K, noise count)
#define Hdim 1024          // reduction dim

#define BM 128
#define BN 128
#define BH 64
#define HSTEPS (Hdim / BH)     // 16
#define NSTAGE 3
#define STAGE_BYTES (4 * 16384)    // Ah,Al,Bh,Bl tiles: 128 rows x 128B each
#define SMEM_TOTAL (NSTAGE * STAGE_BYTES)

// ---------------- static device scratch (no runtime alloc allowed) ----------
__device__ __align__(16) __nv_bfloat16 g_ah[(size_t)Mdim * Hdim];
__device__ __align__(16) __nv_bfloat16 g_al[(size_t)Mdim * Hdim];
__device__ __align__(16) __nv_bfloat16 g_bh[(size_t)Cdim * Hdim];
__device__ __align__(16) __nv_bfloat16 g_bl[(size_t)Cdim * Hdim];
__device__ __align__(16) float g_bn[Cdim];
__device__ __align__(16) float g_pn[Cdim];

// ---------------- helpers ----------------------------------------------------
__device__ __forceinline__ uint32_t smem_u32(const void* p) {
    uint32_t a;
    asm("{ .reg .u64 t; cvta.to.shared.u64 t, %1; cvt.u32.u64 %0, t; }"
        : "=r"(a) : "l"(p));
    return a;
}

#define LDSM4(r, addr) \
    asm volatile("ldmatrix.sync.aligned.m8n8.x4.shared.b16 {%0,%1,%2,%3}, [%4];" \
                 : "=r"((r)[0]), "=r"((r)[1]), "=r"((r)[2]), "=r"((r)[3]) \
                 : "r"(addr))

#define MMA16816(d, a, b0, b1) \
    asm volatile("mma.sync.aligned.m16n8k16.row.col.f32.bf16.bf16.f32 " \
                 "{%0,%1,%2,%3}, {%4,%5,%6,%7}, {%8,%9}, {%0,%1,%2,%3};" \
                 : "+f"((d)[0]), "+f"((d)[1]), "+f"((d)[2]), "+f"((d)[3]) \
                 : "r"((a)[0]), "r"((a)[1]), "r"((a)[2]), "r"((a)[3]), \
                   "r"(b0), "r"(b1))

__device__ __forceinline__ void cp_async16(uint32_t dst, const void* src) {
    asm volatile("cp.async.cg.shared.global [%0], [%1], 16;"
                 :: "r"(dst), "l"(src) : "memory");
}
#define CP_COMMIT() asm volatile("cp.async.commit_group;" ::: "memory")
#define CP_WAIT(n)  asm volatile("cp.async.wait_group %0;" :: "n"(n) : "memory")

// FFMA-only exp (avoids MUFU; rt_SMSP=8 would make 33.5M expf cost ~240us).
__device__ __forceinline__ float fexp(float x) {
    float t = x * 1.4426950408889634f;
    float r = rintf(t);
    float f = t - r;
    float p = 1.5403530393381608e-4f;
    p = fmaf(p, f, 1.3333558146428443e-3f);
    p = fmaf(p, f, 9.6181291076284771e-3f);
    p = fmaf(p, f, 5.5504108664821580e-2f);
    p = fmaf(p, f, 2.4022650695910072e-1f);
    p = fmaf(p, f, 6.9314718055994531e-1f);
    p = fmaf(p, f, 1.0f);
    int e = (int)r;
    return __int_as_float(__float_as_int(p) + (e << 23));
}

// ---------------- preprocessing: fp32 -> bf16 hi/lo ---------------------------
__device__ __forceinline__ void split4(float4 v, uint2& uh, uint2& ul) {
    __nv_bfloat16 h0 = __float2bfloat16(v.x), h1 = __float2bfloat16(v.y);
    __nv_bfloat16 h2 = __float2bfloat16(v.z), h3 = __float2bfloat16(v.w);
    __nv_bfloat16 l0 = __float2bfloat16(v.x - __bfloat162float(h0));
    __nv_bfloat16 l1 = __float2bfloat16(v.y - __bfloat162float(h1));
    __nv_bfloat16 l2 = __float2bfloat16(v.z - __bfloat162float(h2));
    __nv_bfloat16 l3 = __float2bfloat16(v.w - __bfloat162float(h3));
    __nv_bfloat162 a = __halves2bfloat162(h0, h1), b = __halves2bfloat162(h2, h3);
    __nv_bfloat162 c = __halves2bfloat162(l0, l1), d = __halves2bfloat162(l2, l3);
    uh.x = reinterpret_cast<uint32_t&>(a); uh.y = reinterpret_cast<uint32_t&>(b);
    ul.x = reinterpret_cast<uint32_t&>(c); ul.y = reinterpret_cast<uint32_t&>(d);
}

__global__ void split_a_kernel(const float* __restrict__ input) {
    int n = blockIdx.x, t = threadIdx.x;
    float4 v = reinterpret_cast<const float4*>(input + (size_t)n * Hdim)[t];
    uint2 uh, ul; split4(v, uh, ul);
    size_t idx = ((size_t)n * Hdim + t * 4) / 4;
    reinterpret_cast<uint2*>(g_ah)[idx] = uh;
    reinterpret_cast<uint2*>(g_al)[idx] = ul;
}

__global__ void split_b_kernel(const float* __restrict__ weight,
                               const float* __restrict__ bias,
                               const float* __restrict__ up,
                               const int* __restrict__ noise) {
    int k = blockIdx.x, t = threadIdx.x;
    int v = noise[k];
    float4 w = reinterpret_cast<const float4*>(weight + (size_t)v * Hdim)[t];
    uint2 uh, ul; split4(w, uh, ul);
    size_t idx = ((size_t)k * Hdim + t * 4) / 4;
    reinterpret_cast<uint2*>(g_bh)[idx] = uh;
    reinterpret_cast<uint2*>(g_bl)[idx] = ul;
    if (t == 0) { g_bn[k] = bias[v]; g_pn[k] = up[v]; }
}

// ---------------- pmt / pnt ----------------------------------------------------
__global__ void target_kernel(const float* __restrict__ input,
                              const float* __restrict__ weight,
                              const float* __restrict__ bias,
                              const float* __restrict__ up,
                              const int* __restrict__ target,
                              float* __restrict__ out_pmt,
                              float* __restrict__ out_pnt) {
    int n = blockIdx.x * 8 + threadIdx.y;
    int lane = threadIdx.x;
    int tgt = target[n];
    const float4* a = reinterpret_cast<const float4*>(input + (size_t)n * Hdim);
    const float4* w = reinterpret_cast<const float4*>(weight + (size_t)tgt * Hdim);
    float s = 0.f;
#pragma unroll
    for (int j = 0; j < 8; j++) {
        float4 av = a[lane + j * 32];
        float4 wv = w[lane + j * 32];
        s += av.x * wv.x + av.y * wv.y + av.z * wv.z + av.w * wv.w;
    }
#pragma unroll
    for (int o = 16; o; o >>= 1) s += __shfl_xor_sync(0xffffffffu, s, o);
    if (lane == 0) {
        out_pmt[n] = expf(s + bias[tgt]);
        out_pnt[n] = up[tgt];
    }
}

// ---------------- main mma.sync GEMM -------------------------------------------
// pmn[m,c] = fexp(sum_h A[m,h]*Wn[c,h] + bn[c]); pnn[m,c] = pn[c].
// bf16 hi/lo split, 3 products, fp32 accum. 128x128 CTA tile, BK=64, 3-stage.
__global__ __launch_bounds__(256, 1)
void nce_mma(float* __restrict__ out_pmn, float* __restrict__ out_pnn) {
    extern __shared__ uint8_t dynsm[];
    uint32_t smem = smem_u32(dynsm);

    const int tid = threadIdx.x;
    const int lane = tid & 31;
    const int wid = tid >> 5;
    const int wm = wid & 3;           // warp row 0..3  (32 rows each)
    const int wn = wid >> 2;          // warp col 0..1  (64 cols each)

    const int cid = blockIdx.x;
    const int tile_m = cid & 63;      // consecutive CTAs share tile_n -> B reuse
    const int tile_n = cid >> 6;
    const int m0 = tile_m * BM;
    const int c0 = tile_n * BN;

    float acc[2][8][4];
#pragma unroll
    for (int i = 0; i < 2; i++)
#pragma unroll
        for (int j = 0; j < 8; j++)
#pragma unroll
            for (int q = 0; q < 4; q++) acc[i][j][q] = 0.f;

    // ---- stage loader: 4 matrices x 128 rows x 8 chunks of 16B ----
    auto load_stage = [&](int s, int buf) {
        uint32_t sb = smem + buf * STAGE_BYTES;
        const uint8_t* gsrc[4] = {
            reinterpret_cast<const uint8_t*>(g_ah) + (size_t)m0 * 2048,
            reinterpret_cast<const uint8_t*>(g_al) + (size_t)m0 * 2048,
            reinterpret_cast<const uint8_t*>(g_bh) + (size_t)c0 * 2048,
            reinterpret_cast<const uint8_t*>(g_bl) + (size_t)c0 * 2048 };
        int hbyte = s * 128;   // 64 bf16 = 128B per stage along H
#pragma unroll
        for (int mat = 0; mat < 4; mat++) {
            uint32_t mb = sb + mat * 16384;
#pragma unroll
            for (int i = 0; i < 4; i++) {
                int ch = i * 256 + tid;       // 0..1023
                int row = ch >> 3;
                int kc = ch & 7;
                uint32_t dst = mb + row * 128 + ((kc ^ (row & 7)) << 4);
                cp_async16(dst, gsrc[mat] + (size_t)row * 2048 + hbyte + kc * 16);
            }
        }
    };

    // ---- per-stage compute ----
    auto compute_stage = [&](int buf) {
        uint32_t sb = smem + buf * STAGE_BYTES;
        uint32_t a_h = sb, a_l = sb + 16384, b_h = sb + 32768, b_l = sb + 49152;
#pragma unroll
        for (int ks = 0; ks < 4; ks++) {
            uint32_t ah[2][4], al[2][4], bh[4][4], bl[4][4];
#pragma unroll
            for (int mt = 0; mt < 2; mt++) {
                int row = wm * 32 + mt * 16 + (lane & 15);
                int chk = ks * 2 + (lane >> 4);
                uint32_t off = row * 128 + ((chk ^ (row & 7)) << 4);
                LDSM4(ah[mt], a_h + off);
                LDSM4(al[mt], a_l + off);
            }
#pragma unroll
            for (int bp = 0; bp < 4; bp++) {
                int row = wn * 64 + bp * 16 + (lane & 7) + ((lane >> 4) & 1) * 8;
                int chk = ks * 2 + ((lane >> 3) & 1);
                uint32_t off = row * 128 + ((chk ^ (row & 7)) << 4);
                LDSM4(bh[bp], b_h + off);
                LDSM4(bl[bp], b_l + off);
            }
            // products-outer so consecutive mmas hit distinct accumulators
#pragma unroll
            for (int mt = 0; mt < 2; mt++)
#pragma unroll
                for (int bp = 0; bp < 4; bp++) {
                    MMA16816(acc[mt][bp * 2 + 0], ah[mt], bh[bp][0], bh[bp][1]);
                    MMA16816(acc[mt][bp * 2 + 1], ah[mt], bh[bp][2], bh[bp][3]);
                }
#pragma unroll
            for (int mt = 0; mt < 2; mt++)
#pragma unroll
                for (int bp = 0; bp < 4; bp++) {
                    MMA16816(acc[mt][bp * 2 + 0], ah[mt], bl[bp][0], bl[bp][1]);
                    MMA16816(acc[mt][bp * 2 + 1], ah[mt], bl[bp][2], bl[bp][3]);
                }
#pragma unroll
            for (int mt = 0; mt < 2; mt++)
#pragma unroll
                for (int bp = 0; bp < 4; bp++) {
                    MMA16816(acc[mt][bp * 2 + 0], al[mt], bh[bp][0], bh[bp][1]);
                    MMA16816(acc[mt][bp * 2 + 1], al[mt], bh[bp][2], bh[bp][3]);
                }
        }
    };

    load_stage(0, 0); CP_COMMIT();
    load_stage(1, 1); CP_COMMIT();

    for (int s = 0; s < HSTEPS; s++) {
        if (s < HSTEPS - 1) { CP_WAIT(1); } else { CP_WAIT(0); }
        __syncthreads();
        if (s + 2 < HSTEPS) { load_stage(s + 2, (s + 2) % NSTAGE); CP_COMMIT(); }
        compute_stage(s % NSTAGE);
    }

    // ---- epilogue ----
    int g = lane >> 2, tg = lane & 3;
#pragma unroll
    for (int bp = 0; bp < 8; bp++) {
        int col = c0 + wn * 64 + bp * 8 + tg * 2;
        float2 bn = *reinterpret_cast<const float2*>(g_bn + col);
        float2 pn = *reinterpret_cast<const float2*>(g_pn + col);
#pragma unroll
        for (int mt = 0; mt < 2; mt++) {
            int r0 = m0 + wm * 32 + mt * 16 + g;
            float2 e0, e1;
            e0.x = fexp(acc[mt][bp][0] + bn.x);
            e0.y = fexp(acc[mt][bp][1] + bn.y);
            e1.x = fexp(acc[mt][bp][2] + bn.x);
            e1.y = fexp(acc[mt][bp][3] + bn.y);
            *reinterpret_cast<float2*>(out_pmn + (size_t)r0 * Cdim + col) = e0;
            *reinterpret_cast<float2*>(out_pmn + (size_t)(r0 + 8) * Cdim + col) = e1;
            *reinterpret_cast<float2*>(out_pnn + (size_t)r0 * Cdim + col) = pn;
            *reinterpret_cast<float2*>(out_pnn + (size_t)(r0 + 8) * Cdim + col) = pn;
        }
    }
}

// ---------------- launch --------------------------------------------------------
extern "C" void kernel_launch(void* const* d_in, const int* in_sizes, int n_in,
                              void* d_out, int out_size) {
    const float* input  = (const float*)d_in[0];
    const float* weight = (const float*)d_in[1];
    const float* bias   = (const float*)d_in[2];
    const float* up     = (const float*)d_in[3];
    const int*   target = (const int*)d_in[4];
    const int*   noise  = (const int*)d_in[5];

    float* out     = (float*)d_out;
    float* out_pmt = out;
    float* out_pnt = out + Mdim;
    float* out_pmn = out + 2 * Mdim;
    float* out_pnn = out_pmn + (size_t)Mdim * Cdim;

    cudaFuncSetAttribute(nce_mma, cudaFuncAttributeMaxDynamicSharedMemorySize,
                         SMEM_TOTAL);

    split_a_kernel<<<Mdim, 256>>>(input);
    split_b_kernel<<<Cdim, 256>>>(weight, bias, up, noise);
    target_kernel<<<Mdim / 8, dim3(32, 8)>>>(input, weight, bias, up, target,
                                             out_pmt, out_pnt);
    nce_mma<<<(Mdim / BM) * (Cdim / BN), 256, SMEM_TOTAL>>>(out_pmn, out_pnn);
}

// round 4
// speedup vs baseline: 4.0564x; 1.3520x over previous
#include <cuda_runtime.h>
#include <cuda_bf16.h>
#include <cuda_fp16.h>
#include <cstdint>

#define Mdim 8192          // output rows  (problem N)
#define Cdim 4096          // output cols  (problem K, noise count)
#define Hdim 1024          // reduction dim

#define BM 128
#define BN 128
#define BH 64
#define HSTEPS (Hdim / BH)     // 16
#define NSTAGE 4
#define MAT_BYTES 16384        // 128 rows x 64 fp16 (128B rows)
#define STAGE_BYTES (3 * MAT_BYTES)    // Ah, Bh, Bl
#define SMEM_TOTAL (NSTAGE * STAGE_BYTES)   // 192 KB

// ---------------- static device scratch (no runtime alloc allowed) ----------
__device__ __align__(16) __half g_ah[(size_t)Mdim * Hdim];   // fp16(A)
__device__ __align__(16) __half g_bh[(size_t)Cdim * Hdim];   // fp16 hi of 32*Wn
__device__ __align__(16) __half g_bl[(size_t)Cdim * Hdim];   // fp16 lo of 32*Wn
__device__ __align__(16) float g_bn[Cdim];
__device__ __align__(16) float g_pn[Cdim];

// ---------------- helpers ----------------------------------------------------
__device__ __forceinline__ uint32_t smem_u32(const void* p) {
    uint32_t a;
    asm("{ .reg .u64 t; cvta.to.shared.u64 t, %1; cvt.u32.u64 %0, t; }"
        : "=r"(a) : "l"(p));
    return a;
}

#define LDSM4(r, addr) \
    asm volatile("ldmatrix.sync.aligned.m8n8.x4.shared.b16 {%0,%1,%2,%3}, [%4];" \
                 : "=r"((r)[0]), "=r"((r)[1]), "=r"((r)[2]), "=r"((r)[3]) \
                 : "r"(addr))

#define MMA16816(d, a, b0, b1) \
    asm volatile("mma.sync.aligned.m16n8k16.row.col.f32.f16.f16.f32 " \
                 "{%0,%1,%2,%3}, {%4,%5,%6,%7}, {%8,%9}, {%0,%1,%2,%3};" \
                 : "+f"((d)[0]), "+f"((d)[1]), "+f"((d)[2]), "+f"((d)[3]) \
                 : "r"((a)[0]), "r"((a)[1]), "r"((a)[2]), "r"((a)[3]), \
                   "r"(b0), "r"(b1))

__device__ __forceinline__ void cp_async16(uint32_t dst, const void* src) {
    asm volatile("cp.async.cg.shared.global [%0], [%1], 16;"
                 :: "r"(dst), "l"(src) : "memory");
}
#define CP_COMMIT() asm volatile("cp.async.commit_group;" ::: "memory")
#define CP_WAIT(n)  asm volatile("cp.async.wait_group %0;" :: "n"(n) : "memory")

// FFMA-only exp (avoids MUFU throughput wall for 33.5M calls).
__device__ __forceinline__ float fexp(float x) {
    float t = x * 1.4426950408889634f;
    float r = rintf(t);
    float f = t - r;
    float p = 1.5403530393381608e-4f;
    p = fmaf(p, f, 1.3333558146428443e-3f);
    p = fmaf(p, f, 9.6181291076284771e-3f);
    p = fmaf(p, f, 5.5504108664821580e-2f);
    p = fmaf(p, f, 2.4022650695910072e-1f);
    p = fmaf(p, f, 6.9314718055994531e-1f);
    p = fmaf(p, f, 1.0f);
    int e = (int)r;
    return __int_as_float(__float_as_int(p) + (e << 23));
}

// ---------------- preprocessing ------------------------------------------------
__global__ void split_a_kernel(const float* __restrict__ input) {
    int n = blockIdx.x, t = threadIdx.x;
    float4 v = reinterpret_cast<const float4*>(input + (size_t)n * Hdim)[t];
    __half2 p0 = __halves2half2(__float2half_rn(v.x), __float2half_rn(v.y));
    __half2 p1 = __halves2half2(__float2half_rn(v.z), __float2half_rn(v.w));
    uint2 u;
    u.x = reinterpret_cast<uint32_t&>(p0);
    u.y = reinterpret_cast<uint32_t&>(p1);
    reinterpret_cast<uint2*>(g_ah)[((size_t)n * Hdim) / 4 + t] = u;
}

// B is scaled by 32 (exact pow2) so the lo part stays in fp16 normal range.
__global__ void split_b_kernel(const float* __restrict__ weight,
                               const float* __restrict__ bias,
                               const float* __restrict__ up,
                               const int* __restrict__ noise) {
    int k = blockIdx.x, t = threadIdx.x;
    int v = noise[k];
    float4 w = reinterpret_cast<const float4*>(weight + (size_t)v * Hdim)[t];
    w.x *= 32.f; w.y *= 32.f; w.z *= 32.f; w.w *= 32.f;
    __half h0 = __float2half_rn(w.x), h1 = __float2half_rn(w.y);
    __half h2 = __float2half_rn(w.z), h3 = __float2half_rn(w.w);
    __half l0 = __float2half_rn(w.x - __half2float(h0));
    __half l1 = __float2half_rn(w.y - __half2float(h1));
    __half l2 = __float2half_rn(w.z - __half2float(h2));
    __half l3 = __float2half_rn(w.w - __half2float(h3));
    __half2 ph0 = __halves2half2(h0, h1), ph1 = __halves2half2(h2, h3);
    __half2 pl0 = __halves2half2(l0, l1), pl1 = __halves2half2(l2, l3);
    uint2 uh, ul;
    uh.x = reinterpret_cast<uint32_t&>(ph0); uh.y = reinterpret_cast<uint32_t&>(ph1);
    ul.x = reinterpret_cast<uint32_t&>(pl0); ul.y = reinterpret_cast<uint32_t&>(pl1);
    size_t idx = ((size_t)k * Hdim) / 4 + t;
    reinterpret_cast<uint2*>(g_bh)[idx] = uh;
    reinterpret_cast<uint2*>(g_bl)[idx] = ul;
    if (t == 0) { g_bn[k] = bias[v]; g_pn[k] = up[v]; }
}

// ---------------- pmt / pnt ----------------------------------------------------
__global__ void target_kernel(const float* __restrict__ input,
                              const float* __restrict__ weight,
                              const float* __restrict__ bias,
                              const float* __restrict__ up,
                              const int* __restrict__ target,
                              float* __restrict__ out_pmt,
                              float* __restrict__ out_pnt) {
    int n = blockIdx.x * 8 + threadIdx.y;
    int lane = threadIdx.x;
    int tgt = target[n];
    const float4* a = reinterpret_cast<const float4*>(input + (size_t)n * Hdim);
    const float4* w = reinterpret_cast<const float4*>(weight + (size_t)tgt * Hdim);
    float s = 0.f;
#pragma unroll
    for (int j = 0; j < 8; j++) {
        float4 av = a[lane + j * 32];
        float4 wv = w[lane + j * 32];
        s += av.x * wv.x + av.y * wv.y + av.z * wv.z + av.w * wv.w;
    }
#pragma unroll
    for (int o = 16; o; o >>= 1) s += __shfl_xor_sync(0xffffffffu, s, o);
    if (lane == 0) {
        out_pmt[n] = expf(s + bias[tgt]);
        out_pnt[n] = up[tgt];
    }
}

// ---------------- main mma.sync GEMM -------------------------------------------
// pmn[m,c] = fexp((sum_h Ah[m,h]*(Bh+Bl)[c,h]) / 32 + bn[c]); pnn[m,c] = pn[c].
// fp16 A single, B hi/lo split (2 products), fp32 accum. 128x128 tile, BH=64,
// 4-stage cp.async pipeline.
__global__ __launch_bounds__(256, 1)
void nce_mma(float* __restrict__ out_pmn, float* __restrict__ out_pnn) {
    extern __shared__ uint8_t dynsm[];
    uint32_t smem = smem_u32(dynsm);

    const int tid = threadIdx.x;
    const int lane = tid & 31;
    const int wid = tid >> 5;
    const int wm = wid & 3;           // warp row 0..3  (32 rows each)
    const int wn = wid >> 2;          // warp col 0..1  (64 cols each)

    const int cid = blockIdx.x;
    const int tile_m = cid & 63;      // consecutive CTAs share tile_n -> B reuse
    const int tile_n = cid >> 6;
    const int m0 = tile_m * BM;
    const int c0 = tile_n * BN;

    float acc[2][8][4];
#pragma unroll
    for (int i = 0; i < 2; i++)
#pragma unroll
        for (int j = 0; j < 8; j++)
#pragma unroll
            for (int q = 0; q < 4; q++) acc[i][j][q] = 0.f;

    // ---- stage loader: 3 matrices x 128 rows x 8 chunks of 16B ----
    auto load_stage = [&](int s, int buf) {
        uint32_t sb = smem + buf * STAGE_BYTES;
        const uint8_t* gsrc[3] = {
            reinterpret_cast<const uint8_t*>(g_ah) + (size_t)m0 * 2048,
            reinterpret_cast<const uint8_t*>(g_bh) + (size_t)c0 * 2048,
            reinterpret_cast<const uint8_t*>(g_bl) + (size_t)c0 * 2048 };
        int hbyte = s * 128;   // 64 fp16 = 128B per stage along H
#pragma unroll
        for (int mat = 0; mat < 3; mat++) {
            uint32_t mb = sb + mat * MAT_BYTES;
#pragma unroll
            for (int i = 0; i < 4; i++) {
                int ch = i * 256 + tid;       // 0..1023
                int row = ch >> 3;
                int kc = ch & 7;
                uint32_t dst = mb + row * 128 + ((kc ^ (row & 7)) << 4);
                cp_async16(dst, gsrc[mat] + (size_t)row * 2048 + hbyte + kc * 16);
            }
        }
    };

    // ---- per-stage compute ----
    auto compute_stage = [&](int buf) {
        uint32_t sb = smem + buf * STAGE_BYTES;
        uint32_t a_h = sb, b_h = sb + MAT_BYTES, b_l = sb + 2 * MAT_BYTES;
#pragma unroll
        for (int ks = 0; ks < 4; ks++) {
            uint32_t ah[2][4], bh[4][4], bl[4][4];
#pragma unroll
            for (int mt = 0; mt < 2; mt++) {
                int row = wm * 32 + mt * 16 + (lane & 15);
                int chk = ks * 2 + (lane >> 4);
                uint32_t off = row * 128 + ((chk ^ (row & 7)) << 4);
                LDSM4(ah[mt], a_h + off);
            }
#pragma unroll
            for (int bp = 0; bp < 4; bp++) {
                int row = wn * 64 + bp * 16 + (lane & 7) + ((lane >> 4) & 1) * 8;
                int chk = ks * 2 + ((lane >> 3) & 1);
                uint32_t off = row * 128 + ((chk ^ (row & 7)) << 4);
                LDSM4(bh[bp], b_h + off);
                LDSM4(bl[bp], b_l + off);
            }
            // products-outer: same accumulator revisited only every 16 MMAs
#pragma unroll
            for (int mt = 0; mt < 2; mt++)
#pragma unroll
                for (int bp = 0; bp < 4; bp++) {
                    MMA16816(acc[mt][bp * 2 + 0], ah[mt], bh[bp][0], bh[bp][1]);
                    MMA16816(acc[mt][bp * 2 + 1], ah[mt], bh[bp][2], bh[bp][3]);
                }
#pragma unroll
            for (int mt = 0; mt < 2; mt++)
#pragma unroll
                for (int bp = 0; bp < 4; bp++) {
                    MMA16816(acc[mt][bp * 2 + 0], ah[mt], bl[bp][0], bl[bp][1]);
                    MMA16816(acc[mt][bp * 2 + 1], ah[mt], bl[bp][2], bl[bp][3]);
                }
        }
    };

    load_stage(0, 0); CP_COMMIT();
    load_stage(1, 1); CP_COMMIT();
    load_stage(2, 2); CP_COMMIT();

    for (int s = 0; s < HSTEPS; s++) {
        if (s <= HSTEPS - 3)      { CP_WAIT(2); }
        else if (s == HSTEPS - 2) { CP_WAIT(1); }
        else                      { CP_WAIT(0); }
        __syncthreads();
        if (s + 3 < HSTEPS) { load_stage(s + 3, (s + 3) & 3); CP_COMMIT(); }
        compute_stage(s & 3);
    }

    // ---- epilogue: undo the x32 B scaling, add bias, exp ----
    int g = lane >> 2, tg = lane & 3;
#pragma unroll
    for (int bp = 0; bp < 8; bp++) {
        int col = c0 + wn * 64 + bp * 8 + tg * 2;
        float2 bn = *reinterpret_cast<const float2*>(g_bn + col);
        float2 pn = *reinterpret_cast<const float2*>(g_pn + col);
#pragma unroll
        for (int mt = 0; mt < 2; mt++) {
            int r0 = m0 + wm * 32 + mt * 16 + g;
            float2 e0, e1;
            e0.x = fexp(fmaf(acc[mt][bp][0], 0.03125f, bn.x));
            e0.y = fexp(fmaf(acc[mt][bp][1], 0.03125f, bn.y));
            e1.x = fexp(fmaf(acc[mt][bp][2], 0.03125f, bn.x));
            e1.y = fexp(fmaf(acc[mt][bp][3], 0.03125f, bn.y));
            *reinterpret_cast<float2*>(out_pmn + (size_t)r0 * Cdim + col) = e0;
            *reinterpret_cast<float2*>(out_pmn + (size_t)(r0 + 8) * Cdim + col) = e1;
            *reinterpret_cast<float2*>(out_pnn + (size_t)r0 * Cdim + col) = pn;
            *reinterpret_cast<float2*>(out_pnn + (size_t)(r0 + 8) * Cdim + col) = pn;
        }
    }
}

// ---------------- launch --------------------------------------------------------
extern "C" void kernel_launch(void* const* d_in, const int* in_sizes, int n_in,
                              void* d_out, int out_size) {
    const float* input  = (const float*)d_in[0];
    const float* weight = (const float*)d_in[1];
    const float* bias   = (const float*)d_in[2];
    const float* up     = (const float*)d_in[3];
    const int*   target = (const int*)d_in[4];
    const int*   noise  = (const int*)d_in[5];

    float* out     = (float*)d_out;
    float* out_pmt = out;
    float* out_pnt = out + Mdim;
    float* out_pmn = out + 2 * Mdim;
    float* out_pnn = out_pmn + (size_t)Mdim * Cdim;

    cudaFuncSetAttribute(nce_mma, cudaFuncAttributeMaxDynamicSharedMemorySize,
                         SMEM_TOTAL);

    split_a_kernel<<<Mdim, 256>>>(input);
    split_b_kernel<<<Cdim, 256>>>(weight, bias, up, noise);
    target_kernel<<<Mdim / 8, dim3(32, 8)>>>(input, weight, bias, up, target,
                                             out_pmt, out_pnt);
    nce_mma<<<(Mdim / BM) * (Cdim / BN), 256, SMEM_TOTAL>>>(out_pmn, out_pnn);
}

// round 5
// speedup vs baseline: 4.7136x; 1.1620x over previous
#include <cuda_runtime.h>
#include <cuda_bf16.h>
#include <cuda_fp16.h>
#include <cstdint>

#define Mdim 8192          // output rows  (problem N)
#define Cdim 4096          // output cols  (problem K, noise count)
#define Hdim 1024          // reduction dim

#define BM 128
#define BN 128
#define BH 64
#define HSTEPS (Hdim / BH)     // 16
#define NSTAGE 2
#define MAT_BYTES 16384        // 128 rows x 64 fp16 (128B rows)
#define STAGE_BYTES (3 * MAT_BYTES)    // Ah, Bh, Bl
#define SMEM_TOTAL (NSTAGE * STAGE_BYTES)   // 96 KB -> 2 CTAs/SM

// ---------------- static device scratch (no runtime alloc allowed) ----------
__device__ __align__(16) __half g_ah[(size_t)Mdim * Hdim];   // fp16(A)
__device__ __align__(16) __half g_bh[(size_t)Cdim * Hdim];   // fp16 hi of 32*Wn
__device__ __align__(16) __half g_bl[(size_t)Cdim * Hdim];   // fp16 lo of 32*Wn
__device__ __align__(16) float g_bn[Cdim];
__device__ __align__(16) float g_pn[Cdim];

// ---------------- helpers ----------------------------------------------------
__device__ __forceinline__ uint32_t smem_u32(const void* p) {
    uint32_t a;
    asm("{ .reg .u64 t; cvta.to.shared.u64 t, %1; cvt.u32.u64 %0, t; }"
        : "=r"(a) : "l"(p));
    return a;
}

#define LDSM4(r, addr) \
    asm volatile("ldmatrix.sync.aligned.m8n8.x4.shared.b16 {%0,%1,%2,%3}, [%4];" \
                 : "=r"((r)[0]), "=r"((r)[1]), "=r"((r)[2]), "=r"((r)[3]) \
                 : "r"(addr))

#define MMA16816(d, a, b0, b1) \
    asm volatile("mma.sync.aligned.m16n8k16.row.col.f32.f16.f16.f32 " \
                 "{%0,%1,%2,%3}, {%4,%5,%6,%7}, {%8,%9}, {%0,%1,%2,%3};" \
                 : "+f"((d)[0]), "+f"((d)[1]), "+f"((d)[2]), "+f"((d)[3]) \
                 : "r"((a)[0]), "r"((a)[1]), "r"((a)[2]), "r"((a)[3]), \
                   "r"(b0), "r"(b1))

__device__ __forceinline__ void cp_async16(uint32_t dst, const void* src) {
    asm volatile("cp.async.cg.shared.global [%0], [%1], 16;"
                 :: "r"(dst), "l"(src) : "memory");
}
#define CP_COMMIT() asm volatile("cp.async.commit_group;" ::: "memory")
#define CP_WAIT(n)  asm volatile("cp.async.wait_group %0;" :: "n"(n) : "memory")

// FFMA-only exp (avoids MUFU throughput wall for 33.5M calls).
__device__ __forceinline__ float fexp(float x) {
    float t = x * 1.4426950408889634f;
    float r = rintf(t);
    float f = t - r;
    float p = 1.5403530393381608e-4f;
    p = fmaf(p, f, 1.3333558146428443e-3f);
    p = fmaf(p, f, 9.6181291076284771e-3f);
    p = fmaf(p, f, 5.5504108664821580e-2f);
    p = fmaf(p, f, 2.4022650695910072e-1f);
    p = fmaf(p, f, 6.9314718055994531e-1f);
    p = fmaf(p, f, 1.0f);
    int e = (int)r;
    return __int_as_float(__float_as_int(p) + (e << 23));
}

// ---------------- preprocessing ------------------------------------------------
__global__ void split_a_kernel(const float* __restrict__ input) {
    int n = blockIdx.x, t = threadIdx.x;
    float4 v = reinterpret_cast<const float4*>(input + (size_t)n * Hdim)[t];
    __half2 p0 = __halves2half2(__float2half_rn(v.x), __float2half_rn(v.y));
    __half2 p1 = __halves2half2(__float2half_rn(v.z), __float2half_rn(v.w));
    uint2 u;
    u.x = reinterpret_cast<uint32_t&>(p0);
    u.y = reinterpret_cast<uint32_t&>(p1);
    reinterpret_cast<uint2*>(g_ah)[((size_t)n * Hdim) / 4 + t] = u;
}

// B is scaled by 32 (exact pow2) so the lo part stays in fp16 normal range.
__global__ void split_b_kernel(const float* __restrict__ weight,
                               const float* __restrict__ bias,
                               const float* __restrict__ up,
                               const int* __restrict__ noise) {
    int k = blockIdx.x, t = threadIdx.x;
    int v = noise[k];
    float4 w = reinterpret_cast<const float4*>(weight + (size_t)v * Hdim)[t];
    w.x *= 32.f; w.y *= 32.f; w.z *= 32.f; w.w *= 32.f;
    __half h0 = __float2half_rn(w.x), h1 = __float2half_rn(w.y);
    __half h2 = __float2half_rn(w.z), h3 = __float2half_rn(w.w);
    __half l0 = __float2half_rn(w.x - __half2float(h0));
    __half l1 = __float2half_rn(w.y - __half2float(h1));
    __half l2 = __float2half_rn(w.z - __half2float(h2));
    __half l3 = __float2half_rn(w.w - __half2float(h3));
    __half2 ph0 = __halves2half2(h0, h1), ph1 = __halves2half2(h2, h3);
    __half2 pl0 = __halves2half2(l0, l1), pl1 = __halves2half2(l2, l3);
    uint2 uh, ul;
    uh.x = reinterpret_cast<uint32_t&>(ph0); uh.y = reinterpret_cast<uint32_t&>(ph1);
    ul.x = reinterpret_cast<uint32_t&>(pl0); ul.y = reinterpret_cast<uint32_t&>(pl1);
    size_t idx = ((size_t)k * Hdim) / 4 + t;
    reinterpret_cast<uint2*>(g_bh)[idx] = uh;
    reinterpret_cast<uint2*>(g_bl)[idx] = ul;
    if (t == 0) { g_bn[k] = bias[v]; g_pn[k] = up[v]; }
}

// ---------------- pmt / pnt ----------------------------------------------------
__global__ void target_kernel(const float* __restrict__ input,
                              const float* __restrict__ weight,
                              const float* __restrict__ bias,
                              const float* __restrict__ up,
                              const int* __restrict__ target,
                              float* __restrict__ out_pmt,
                              float* __restrict__ out_pnt) {
    int n = blockIdx.x * 8 + threadIdx.y;
    int lane = threadIdx.x;
    int tgt = target[n];
    const float4* a = reinterpret_cast<const float4*>(input + (size_t)n * Hdim);
    const float4* w = reinterpret_cast<const float4*>(weight + (size_t)tgt * Hdim);
    float s = 0.f;
#pragma unroll
    for (int j = 0; j < 8; j++) {
        float4 av = a[lane + j * 32];
        float4 wv = w[lane + j * 32];
        s += av.x * wv.x + av.y * wv.y + av.z * wv.z + av.w * wv.w;
    }
#pragma unroll
    for (int o = 16; o; o >>= 1) s += __shfl_xor_sync(0xffffffffu, s, o);
    if (lane == 0) {
        out_pmt[n] = expf(s + bias[tgt]);
        out_pnt[n] = up[tgt];
    }
}

// ---------------- main mma.sync GEMM -------------------------------------------
// pmn[m,c] = fexp((sum_h Ah[m,h]*(Bh+Bl)[c,h]) / 32 + bn[c]); pnn[m,c] = pn[c].
// 128x128 CTA tile, 8 warps of 64x32, BH=64, double-buffered, 2 CTAs/SM.
__global__ __launch_bounds__(256, 2)
void nce_mma(float* __restrict__ out_pmn, float* __restrict__ out_pnn) {
    extern __shared__ uint8_t dynsm[];
    uint32_t smem = smem_u32(dynsm);

    const int tid = threadIdx.x;
    const int lane = tid & 31;
    const int wid = tid >> 5;
    const int wm = wid & 1;           // warp row 0..1  (64 rows each)
    const int wn = wid >> 1;          // warp col 0..3  (32 cols each)

    const int cid = blockIdx.x;
    const int tile_m = cid & 63;      // consecutive CTAs share tile_n -> B reuse
    const int tile_n = cid >> 6;
    const int m0 = tile_m * BM;
    const int c0 = tile_n * BN;

    float acc[4][4][4];
#pragma unroll
    for (int i = 0; i < 4; i++)
#pragma unroll
        for (int j = 0; j < 4; j++)
#pragma unroll
            for (int q = 0; q < 4; q++) acc[i][j][q] = 0.f;

    // ---- stage loader: 3 matrices x 128 rows x 8 chunks of 16B ----
    auto load_stage = [&](int s, int buf) {
        uint32_t sb = smem + buf * STAGE_BYTES;
        const uint8_t* gsrc[3] = {
            reinterpret_cast<const uint8_t*>(g_ah) + (size_t)m0 * 2048,
            reinterpret_cast<const uint8_t*>(g_bh) + (size_t)c0 * 2048,
            reinterpret_cast<const uint8_t*>(g_bl) + (size_t)c0 * 2048 };
        int hbyte = s * 128;   // 64 fp16 = 128B per stage along H
#pragma unroll
        for (int mat = 0; mat < 3; mat++) {
            uint32_t mb = sb + mat * MAT_BYTES;
#pragma unroll
            for (int i = 0; i < 4; i++) {
                int ch = i * 256 + tid;       // 0..1023
                int row = ch >> 3;
                int kc = ch & 7;
                uint32_t dst = mb + row * 128 + ((kc ^ (row & 7)) << 4);
                cp_async16(dst, gsrc[mat] + (size_t)row * 2048 + hbyte + kc * 16);
            }
        }
    };

    // ---- per-stage compute: warp tile 64x32, 8 LDSM / 32 MMA per ks ----
    auto compute_stage = [&](int buf) {
        uint32_t sb = smem + buf * STAGE_BYTES;
        uint32_t a_h = sb, b_h = sb + MAT_BYTES, b_l = sb + 2 * MAT_BYTES;
#pragma unroll
        for (int ks = 0; ks < 4; ks++) {
            uint32_t ah[4][4], bh[2][4], bl[2][4];
#pragma unroll
            for (int mt = 0; mt < 4; mt++) {
                int row = wm * 64 + mt * 16 + (lane & 15);
                int chk = ks * 2 + (lane >> 4);
                uint32_t off = row * 128 + ((chk ^ (row & 7)) << 4);
                LDSM4(ah[mt], a_h + off);
            }
#pragma unroll
            for (int bp = 0; bp < 2; bp++) {
                int row = wn * 32 + bp * 16 + (lane & 7) + ((lane >> 4) & 1) * 8;
                int chk = ks * 2 + ((lane >> 3) & 1);
                uint32_t off = row * 128 + ((chk ^ (row & 7)) << 4);
                LDSM4(bh[bp], b_h + off);
                LDSM4(bl[bp], b_l + off);
            }
            // products-outer: an accumulator is revisited only every 16 MMAs
#pragma unroll
            for (int mt = 0; mt < 4; mt++)
#pragma unroll
                for (int bp = 0; bp < 2; bp++) {
                    MMA16816(acc[mt][bp * 2 + 0], ah[mt], bh[bp][0], bh[bp][1]);
                    MMA16816(acc[mt][bp * 2 + 1], ah[mt], bh[bp][2], bh[bp][3]);
                }
#pragma unroll
            for (int mt = 0; mt < 4; mt++)
#pragma unroll
                for (int bp = 0; bp < 2; bp++) {
                    MMA16816(acc[mt][bp * 2 + 0], ah[mt], bl[bp][0], bl[bp][1]);
                    MMA16816(acc[mt][bp * 2 + 1], ah[mt], bl[bp][2], bl[bp][3]);
                }
        }
    };

    load_stage(0, 0); CP_COMMIT();

    for (int s = 0; s < HSTEPS; s++) {
        CP_WAIT(0);                 // stage s resident
        __syncthreads();            // all warps done reading buffer (s+1)&1
        if (s + 1 < HSTEPS) { load_stage(s + 1, (s + 1) & 1); CP_COMMIT(); }
        compute_stage(s & 1);       // overlaps with load of s+1
    }

    // ---- epilogue: undo the x32 B scaling, add bias, exp ----
    int g = lane >> 2, tg = lane & 3;
#pragma unroll
    for (int bp = 0; bp < 4; bp++) {
        int col = c0 + wn * 32 + bp * 8 + tg * 2;
        float2 bn = *reinterpret_cast<const float2*>(g_bn + col);
        float2 pn = *reinterpret_cast<const float2*>(g_pn + col);
#pragma unroll
        for (int mt = 0; mt < 4; mt++) {
            int r0 = m0 + wm * 64 + mt * 16 + g;
            float2 e0, e1;
            e0.x = fexp(fmaf(acc[mt][bp][0], 0.03125f, bn.x));
            e0.y = fexp(fmaf(acc[mt][bp][1], 0.03125f, bn.y));
            e1.x = fexp(fmaf(acc[mt][bp][2], 0.03125f, bn.x));
            e1.y = fexp(fmaf(acc[mt][bp][3], 0.03125f, bn.y));
            *reinterpret_cast<float2*>(out_pmn + (size_t)r0 * Cdim + col) = e0;
            *reinterpret_cast<float2*>(out_pmn + (size_t)(r0 + 8) * Cdim + col) = e1;
            *reinterpret_cast<float2*>(out_pnn + (size_t)r0 * Cdim + col) = pn;
            *reinterpret_cast<float2*>(out_pnn + (size_t)(r0 + 8) * Cdim + col) = pn;
        }
    }
}

// ---------------- launch --------------------------------------------------------
extern "C" void kernel_launch(void* const* d_in, const int* in_sizes, int n_in,
                              void* d_out, int out_size) {
    const float* input  = (const float*)d_in[0];
    const float* weight = (const float*)d_in[1];
    const float* bias   = (const float*)d_in[2];
    const float* up     = (const float*)d_in[3];
    const int*   target = (const int*)d_in[4];
    const int*   noise  = (const int*)d_in[5];

    float* out     = (float*)d_out;
    float* out_pmt = out;
    float* out_pnt = out + Mdim;
    float* out_pmn = out + 2 * Mdim;
    float* out_pnn = out_pmn + (size_t)Mdim * Cdim;

    cudaFuncSetAttribute(nce_mma, cudaFuncAttributeMaxDynamicSharedMemorySize,
                         SMEM_TOTAL);

    split_a_kernel<<<Mdim, 256>>>(input);
    split_b_kernel<<<Cdim, 256>>>(weight, bias, up, noise);
    target_kernel<<<Mdim / 8, dim3(32, 8)>>>(input, weight, bias, up, target,
                                             out_pmt, out_pnt);
    nce_mma<<<(Mdim / BM) * (Cdim / BN), 256, SMEM_TOTAL>>>(out_pmn, out_pnn);
}

// round 6
// speedup vs baseline: 7.1820x; 1.5237x over previous
#include <cuda_runtime.h>
#include <cuda_bf16.h>
#include <cuda_fp16.h>
#include <cstdint>

#define Mdim 8192          // output rows  (problem N)
#define Cdim 4096          // output cols  (problem K, noise count)
#define Hdim 1024          // reduction dim

#define BM 128
#define BN 128
#define BH 64
#define HSTEPS (Hdim / BH)     // 16
#define NSTAGE 3
#define MAT_BYTES 16384        // 128 rows x 64 fp16 (128B rows)
#define STAGE_BYTES (2 * MAT_BYTES)        // Ah, Bh
#define SMEM_TOTAL (NSTAGE * STAGE_BYTES)  // 96 KB -> 2 CTAs/SM

// ---------------- static device scratch (no runtime alloc allowed) ----------
__device__ __align__(16) __half g_ah[(size_t)Mdim * Hdim];   // fp16(A)
__device__ __align__(16) __half g_bh[(size_t)Cdim * Hdim];   // fp16(Wn)
__device__ __align__(16) float g_bn[Cdim];
__device__ __align__(16) float g_pn[Cdim];

// ---------------- helpers ----------------------------------------------------
__device__ __forceinline__ uint32_t smem_u32(const void* p) {
    uint32_t a;
    asm("{ .reg .u64 t; cvta.to.shared.u64 t, %1; cvt.u32.u64 %0, t; }"
        : "=r"(a) : "l"(p));
    return a;
}

#define LDSM4(r, addr) \
    asm volatile("ldmatrix.sync.aligned.m8n8.x4.shared.b16 {%0,%1,%2,%3}, [%4];" \
                 : "=r"((r)[0]), "=r"((r)[1]), "=r"((r)[2]), "=r"((r)[3]) \
                 : "r"(addr))

#define MMA16816(d, a, b0, b1) \
    asm volatile("mma.sync.aligned.m16n8k16.row.col.f32.f16.f16.f32 " \
                 "{%0,%1,%2,%3}, {%4,%5,%6,%7}, {%8,%9}, {%0,%1,%2,%3};" \
                 : "+f"((d)[0]), "+f"((d)[1]), "+f"((d)[2]), "+f"((d)[3]) \
                 : "r"((a)[0]), "r"((a)[1]), "r"((a)[2]), "r"((a)[3]), \
                   "r"(b0), "r"(b1))

__device__ __forceinline__ void cp_async16(uint32_t dst, const void* src) {
    asm volatile("cp.async.cg.shared.global [%0], [%1], 16;"
                 :: "r"(dst), "l"(src) : "memory");
}
#define CP_COMMIT() asm volatile("cp.async.commit_group;" ::: "memory")
#define CP_WAIT(n)  asm volatile("cp.async.wait_group %0;" :: "n"(n) : "memory")

// FFMA-only exp (avoids MUFU throughput wall for 33.5M calls).
__device__ __forceinline__ float fexp(float x) {
    float t = x * 1.4426950408889634f;
    float r = rintf(t);
    float f = t - r;
    float p = 1.5403530393381608e-4f;
    p = fmaf(p, f, 1.3333558146428443e-3f);
    p = fmaf(p, f, 9.6181291076284771e-3f);
    p = fmaf(p, f, 5.5504108664821580e-2f);
    p = fmaf(p, f, 2.4022650695910072e-1f);
    p = fmaf(p, f, 6.9314718055994531e-1f);
    p = fmaf(p, f, 1.0f);
    int e = (int)r;
    return __int_as_float(__float_as_int(p) + (e << 23));
}

// ---------------- preprocessing ------------------------------------------------
__global__ void split_a_kernel(const float* __restrict__ input) {
    int n = blockIdx.x, t = threadIdx.x;
    float4 v = reinterpret_cast<const float4*>(input + (size_t)n * Hdim)[t];
    __half2 p0 = __halves2half2(__float2half_rn(v.x), __float2half_rn(v.y));
    __half2 p1 = __halves2half2(__float2half_rn(v.z), __float2half_rn(v.w));
    uint2 u;
    u.x = reinterpret_cast<uint32_t&>(p0);
    u.y = reinterpret_cast<uint32_t&>(p1);
    reinterpret_cast<uint2*>(g_ah)[((size_t)n * Hdim) / 4 + t] = u;
}

__global__ void split_b_kernel(const float* __restrict__ weight,
                               const float* __restrict__ bias,
                               const float* __restrict__ up,
                               const int* __restrict__ noise) {
    int k = blockIdx.x, t = threadIdx.x;
    int v = noise[k];
    float4 w = reinterpret_cast<const float4*>(weight + (size_t)v * Hdim)[t];
    __half2 p0 = __halves2half2(__float2half_rn(w.x), __float2half_rn(w.y));
    __half2 p1 = __halves2half2(__float2half_rn(w.z), __float2half_rn(w.w));
    uint2 u;
    u.x = reinterpret_cast<uint32_t&>(p0);
    u.y = reinterpret_cast<uint32_t&>(p1);
    reinterpret_cast<uint2*>(g_bh)[((size_t)k * Hdim) / 4 + t] = u;
    if (t == 0) { g_bn[k] = bias[v]; g_pn[k] = up[v]; }
}

// ---------------- pmt / pnt ----------------------------------------------------
__global__ void target_kernel(const float* __restrict__ input,
                              const float* __restrict__ weight,
                              const float* __restrict__ bias,
                              const float* __restrict__ up,
                              const int* __restrict__ target,
                              float* __restrict__ out_pmt,
                              float* __restrict__ out_pnt) {
    int n = blockIdx.x * 8 + threadIdx.y;
    int lane = threadIdx.x;
    int tgt = target[n];
    const float4* a = reinterpret_cast<const float4*>(input + (size_t)n * Hdim);
    const float4* w = reinterpret_cast<const float4*>(weight + (size_t)tgt * Hdim);
    float s = 0.f;
#pragma unroll
    for (int j = 0; j < 8; j++) {
        float4 av = a[lane + j * 32];
        float4 wv = w[lane + j * 32];
        s += av.x * wv.x + av.y * wv.y + av.z * wv.z + av.w * wv.w;
    }
#pragma unroll
    for (int o = 16; o; o >>= 1) s += __shfl_xor_sync(0xffffffffu, s, o);
    if (lane == 0) {
        out_pmt[n] = expf(s + bias[tgt]);
        out_pnt[n] = up[tgt];
    }
}

// ---------------- main mma.sync GEMM -------------------------------------------
// pmn[m,c] = fexp(sum_h Ah[m,h]*Bh[c,h] + bn[c]); pnn[m,c] = pn[c].
// Plain fp16 single product (norm-err ~1.7e-4, 6x under threshold).
// 128x128 CTA tile, 8 warps of 64x32, BH=64, 3-stage pipeline, 2 CTAs/SM.
__global__ __launch_bounds__(256, 2)
void nce_mma(float* __restrict__ out_pmn, float* __restrict__ out_pnn) {
    extern __shared__ uint8_t dynsm[];
    uint32_t smem = smem_u32(dynsm);

    const int tid = threadIdx.x;
    const int lane = tid & 31;
    const int wid = tid >> 5;
    const int wm = wid & 1;           // warp row 0..1  (64 rows each)
    const int wn = wid >> 1;          // warp col 0..3  (32 cols each)

    const int cid = blockIdx.x;
    const int tile_m = cid & 63;      // consecutive CTAs share tile_n -> B reuse
    const int tile_n = cid >> 6;
    const int m0 = tile_m * BM;
    const int c0 = tile_n * BN;

    float acc[4][4][4];
#pragma unroll
    for (int i = 0; i < 4; i++)
#pragma unroll
        for (int j = 0; j < 4; j++)
#pragma unroll
            for (int q = 0; q < 4; q++) acc[i][j][q] = 0.f;

    // ---- stage loader: 2 matrices x 128 rows x 8 chunks of 16B ----
    auto load_stage = [&](int s, int buf) {
        uint32_t sb = smem + buf * STAGE_BYTES;
        const uint8_t* gsrc[2] = {
            reinterpret_cast<const uint8_t*>(g_ah) + (size_t)m0 * 2048,
            reinterpret_cast<const uint8_t*>(g_bh) + (size_t)c0 * 2048 };
        int hbyte = s * 128;   // 64 fp16 = 128B per stage along H
#pragma unroll
        for (int mat = 0; mat < 2; mat++) {
            uint32_t mb = sb + mat * MAT_BYTES;
#pragma unroll
            for (int i = 0; i < 4; i++) {
                int ch = i * 256 + tid;       // 0..1023
                int row = ch >> 3;
                int kc = ch & 7;
                uint32_t dst = mb + row * 128 + ((kc ^ (row & 7)) << 4);
                cp_async16(dst, gsrc[mat] + (size_t)row * 2048 + hbyte + kc * 16);
            }
        }
    };

    // ---- per-stage compute: warp tile 64x32, 6 LDSM / 16 MMA per ks ----
    auto compute_stage = [&](int buf) {
        uint32_t sb = smem + buf * STAGE_BYTES;
        uint32_t a_h = sb, b_h = sb + MAT_BYTES;
#pragma unroll
        for (int ks = 0; ks < 4; ks++) {
            uint32_t ah[4][4], bh[2][4];
#pragma unroll
            for (int mt = 0; mt < 4; mt++) {
                int row = wm * 64 + mt * 16 + (lane & 15);
                int chk = ks * 2 + (lane >> 4);
                uint32_t off = row * 128 + ((chk ^ (row & 7)) << 4);
                LDSM4(ah[mt], a_h + off);
            }
#pragma unroll
            for (int bp = 0; bp < 2; bp++) {
                int row = wn * 32 + bp * 16 + (lane & 7) + ((lane >> 4) & 1) * 8;
                int chk = ks * 2 + ((lane >> 3) & 1);
                uint32_t off = row * 128 + ((chk ^ (row & 7)) << 4);
                LDSM4(bh[bp], b_h + off);
            }
#pragma unroll
            for (int mt = 0; mt < 4; mt++)
#pragma unroll
                for (int bp = 0; bp < 2; bp++) {
                    MMA16816(acc[mt][bp * 2 + 0], ah[mt], bh[bp][0], bh[bp][1]);
                    MMA16816(acc[mt][bp * 2 + 1], ah[mt], bh[bp][2], bh[bp][3]);
                }
        }
    };

    load_stage(0, 0); CP_COMMIT();
    load_stage(1, 1); CP_COMMIT();

    for (int s = 0; s < HSTEPS; s++) {
        if (s < HSTEPS - 1) { CP_WAIT(1); } else { CP_WAIT(0); }
        __syncthreads();            // stage s resident; buffer (s+2)%3 free
        if (s + 2 < HSTEPS) { load_stage(s + 2, (s + 2) % NSTAGE); CP_COMMIT(); }
        compute_stage(s % NSTAGE);  // overlaps with in-flight load
    }

    // ---- epilogue: add bias, exp ----
    int g = lane >> 2, tg = lane & 3;
#pragma unroll
    for (int bp = 0; bp < 4; bp++) {
        int col = c0 + wn * 32 + bp * 8 + tg * 2;
        float2 bn = *reinterpret_cast<const float2*>(g_bn + col);
        float2 pn = *reinterpret_cast<const float2*>(g_pn + col);
#pragma unroll
        for (int mt = 0; mt < 4; mt++) {
            int r0 = m0 + wm * 64 + mt * 16 + g;
            float2 e0, e1;
            e0.x = fexp(acc[mt][bp][0] + bn.x);
            e0.y = fexp(acc[mt][bp][1] + bn.y);
            e1.x = fexp(acc[mt][bp][2] + bn.x);
            e1.y = fexp(acc[mt][bp][3] + bn.y);
            *reinterpret_cast<float2*>(out_pmn + (size_t)r0 * Cdim + col) = e0;
            *reinterpret_cast<float2*>(out_pmn + (size_t)(r0 + 8) * Cdim + col) = e1;
            *reinterpret_cast<float2*>(out_pnn + (size_t)r0 * Cdim + col) = pn;
            *reinterpret_cast<float2*>(out_pnn + (size_t)(r0 + 8) * Cdim + col) = pn;
        }
    }
}

// ---------------- launch --------------------------------------------------------
extern "C" void kernel_launch(void* const* d_in, const int* in_sizes, int n_in,
                              void* d_out, int out_size) {
    const float* input  = (const float*)d_in[0];
    const float* weight = (const float*)d_in[1];
    const float* bias   = (const float*)d_in[2];
    const float* up     = (const float*)d_in[3];
    const int*   target = (const int*)d_in[4];
    const int*   noise  = (const int*)d_in[5];

    float* out     = (float*)d_out;
    float* out_pmt = out;
    float* out_pnt = out + Mdim;
    float* out_pmn = out + 2 * Mdim;
    float* out_pnn = out_pmn + (size_t)Mdim * Cdim;

    cudaFuncSetAttribute(nce_mma, cudaFuncAttributeMaxDynamicSharedMemorySize,
                         SMEM_TOTAL);

    split_a_kernel<<<Mdim, 256>>>(input);
    split_b_kernel<<<Cdim, 256>>>(weight, bias, up, noise);
    target_kernel<<<Mdim / 8, dim3(32, 8)>>>(input, weight, bias, up, target,
                                             out_pmt, out_pnt);
    nce_mma<<<(Mdim / BM) * (Cdim / BN), 256, SMEM_TOTAL>>>(out_pmn, out_pnn);
}

// round 7
// speedup vs baseline: 7.3327x; 1.0210x over previous
#include <cuda_runtime.h>
#include <cuda_bf16.h>
#include <cuda_fp16.h>
#include <cstdint>

#define Mdim 8192          // output rows  (problem N)
#define Cdim 4096          // output cols  (problem K, noise count)
#define Hdim 1024          // reduction dim

#define BM 128
#define BN 128
#define BH 64
#define HSTEPS (Hdim / BH)     // 16
#define NSTAGE 3
#define MAT_BYTES 16384        // 128 rows x 64 fp16 (128B rows)
#define STAGE_BYTES (2 * MAT_BYTES)        // Ah, Bh
#define SMEM_TOTAL (NSTAGE * STAGE_BYTES)  // 96 KB -> 2 CTAs/SM

// ---------------- static device scratch (no runtime alloc allowed) ----------
__device__ __align__(16) __half g_ah[(size_t)Mdim * Hdim];   // fp16(A)
__device__ __align__(16) __half g_bh[(size_t)Cdim * Hdim];   // fp16(Wn)
__device__ __align__(16) float g_bn[Cdim];
__device__ __align__(16) float g_pn[Cdim];

// ---------------- helpers ----------------------------------------------------
__device__ __forceinline__ uint32_t smem_u32(const void* p) {
    uint32_t a;
    asm("{ .reg .u64 t; cvta.to.shared.u64 t, %1; cvt.u32.u64 %0, t; }"
        : "=r"(a) : "l"(p));
    return a;
}

#define LDSM4(r, addr) \
    asm volatile("ldmatrix.sync.aligned.m8n8.x4.shared.b16 {%0,%1,%2,%3}, [%4];" \
                 : "=r"((r)[0]), "=r"((r)[1]), "=r"((r)[2]), "=r"((r)[3]) \
                 : "r"(addr))

#define MMA16816(d, a, b0, b1) \
    asm volatile("mma.sync.aligned.m16n8k16.row.col.f32.f16.f16.f32 " \
                 "{%0,%1,%2,%3}, {%4,%5,%6,%7}, {%8,%9}, {%0,%1,%2,%3};" \
                 : "+f"((d)[0]), "+f"((d)[1]), "+f"((d)[2]), "+f"((d)[3]) \
                 : "r"((a)[0]), "r"((a)[1]), "r"((a)[2]), "r"((a)[3]), \
                   "r"(b0), "r"(b1))

__device__ __forceinline__ void cp_async16(uint32_t dst, const void* src) {
    asm volatile("cp.async.cg.shared.global [%0], [%1], 16;"
                 :: "r"(dst), "l"(src) : "memory");
}
#define CP_COMMIT() asm volatile("cp.async.commit_group;" ::: "memory")
#define CP_WAIT(n)  asm volatile("cp.async.wait_group %0;" :: "n"(n) : "memory")

// FFMA-only exp (avoids MUFU throughput wall for 33.5M calls).
__device__ __forceinline__ float fexp(float x) {
    float t = x * 1.4426950408889634f;
    float r = rintf(t);
    float f = t - r;
    float p = 1.5403530393381608e-4f;
    p = fmaf(p, f, 1.3333558146428443e-3f);
    p = fmaf(p, f, 9.6181291076284771e-3f);
    p = fmaf(p, f, 5.5504108664821580e-2f);
    p = fmaf(p, f, 2.4022650695910072e-1f);
    p = fmaf(p, f, 6.9314718055994531e-1f);
    p = fmaf(p, f, 1.0f);
    int e = (int)r;
    return __int_as_float(__float_as_int(p) + (e << 23));
}

// ---------------- preprocessing ------------------------------------------------
__global__ void split_a_kernel(const float* __restrict__ input) {
    int n = blockIdx.x, t = threadIdx.x;
    float4 v = reinterpret_cast<const float4*>(input + (size_t)n * Hdim)[t];
    __half2 p0 = __halves2half2(__float2half_rn(v.x), __float2half_rn(v.y));
    __half2 p1 = __halves2half2(__float2half_rn(v.z), __float2half_rn(v.w));
    uint2 u;
    u.x = reinterpret_cast<uint32_t&>(p0);
    u.y = reinterpret_cast<uint32_t&>(p1);
    reinterpret_cast<uint2*>(g_ah)[((size_t)n * Hdim) / 4 + t] = u;
}

__global__ void split_b_kernel(const float* __restrict__ weight,
                               const float* __restrict__ bias,
                               const float* __restrict__ up,
                               const int* __restrict__ noise) {
    int k = blockIdx.x, t = threadIdx.x;
    int v = noise[k];
    float4 w = reinterpret_cast<const float4*>(weight + (size_t)v * Hdim)[t];
    __half2 p0 = __halves2half2(__float2half_rn(w.x), __float2half_rn(w.y));
    __half2 p1 = __halves2half2(__float2half_rn(w.z), __float2half_rn(w.w));
    uint2 u;
    u.x = reinterpret_cast<uint32_t&>(p0);
    u.y = reinterpret_cast<uint32_t&>(p1);
    reinterpret_cast<uint2*>(g_bh)[((size_t)k * Hdim) / 4 + t] = u;
    if (t == 0) { g_bn[k] = bias[v]; g_pn[k] = up[v]; }
}

// ---------------- pmt / pnt ----------------------------------------------------
__global__ void target_kernel(const float* __restrict__ input,
                              const float* __restrict__ weight,
                              const float* __restrict__ bias,
                              const float* __restrict__ up,
                              const int* __restrict__ target,
                              float* __restrict__ out_pmt,
                              float* __restrict__ out_pnt) {
    int n = blockIdx.x * 8 + threadIdx.y;
    int lane = threadIdx.x;
    int tgt = target[n];
    const float4* a = reinterpret_cast<const float4*>(input + (size_t)n * Hdim);
    const float4* w = reinterpret_cast<const float4*>(weight + (size_t)tgt * Hdim);
    float s = 0.f;
#pragma unroll
    for (int j = 0; j < 8; j++) {
        float4 av = a[lane + j * 32];
        float4 wv = w[lane + j * 32];
        s += av.x * wv.x + av.y * wv.y + av.z * wv.z + av.w * wv.w;
    }
#pragma unroll
    for (int o = 16; o; o >>= 1) s += __shfl_xor_sync(0xffffffffu, s, o);
    if (lane == 0) {
        out_pmt[n] = expf(s + bias[tgt]);
        out_pnt[n] = up[tgt];
    }
}

// ---------------- main mma.sync GEMM -------------------------------------------
// pmn[m,c] = fexp(sum_h Ah[m,h]*Bh[c,h] + bn[c]); pnn[m,c] = pn[c].
// 128x128 CTA tile, 4 warps of 64x64 (2x2 grid), 128 threads, BH=64,
// 3-stage pipeline, 2 CTAs/SM. smem traffic: 160B/MMA vs 256B budget.
__global__ __launch_bounds__(128, 2)
void nce_mma(float* __restrict__ out_pmn, float* __restrict__ out_pnn) {
    extern __shared__ uint8_t dynsm[];
    uint32_t smem = smem_u32(dynsm);

    const int tid = threadIdx.x;
    const int lane = tid & 31;
    const int wid = tid >> 5;
    const int wm = wid & 1;           // warp row 0..1  (64 rows each)
    const int wn = wid >> 1;          // warp col 0..1  (64 cols each)

    const int cid = blockIdx.x;
    const int tile_m = cid & 63;      // consecutive CTAs share tile_n -> B reuse
    const int tile_n = cid >> 6;
    const int m0 = tile_m * BM;
    const int c0 = tile_n * BN;

    float acc[4][8][4];
#pragma unroll
    for (int i = 0; i < 4; i++)
#pragma unroll
        for (int j = 0; j < 8; j++)
#pragma unroll
            for (int q = 0; q < 4; q++) acc[i][j][q] = 0.f;

    // ---- stage loader: 2 matrices x 128 rows x 8 chunks of 16B, 128 threads ----
    auto load_stage = [&](int s, int buf) {
        uint32_t sb = smem + buf * STAGE_BYTES;
        const uint8_t* gsrc[2] = {
            reinterpret_cast<const uint8_t*>(g_ah) + (size_t)m0 * 2048,
            reinterpret_cast<const uint8_t*>(g_bh) + (size_t)c0 * 2048 };
        int hbyte = s * 128;   // 64 fp16 = 128B per stage along H
#pragma unroll
        for (int mat = 0; mat < 2; mat++) {
            uint32_t mb = sb + mat * MAT_BYTES;
#pragma unroll
            for (int i = 0; i < 8; i++) {
                int ch = i * 128 + tid;       // 0..1023
                int row = ch >> 3;
                int kc = ch & 7;
                uint32_t dst = mb + row * 128 + ((kc ^ (row & 7)) << 4);
                cp_async16(dst, gsrc[mat] + (size_t)row * 2048 + hbyte + kc * 16);
            }
        }
    };

    // ---- per-stage compute: warp tile 64x64, 8 LDSM / 32 MMA per ks ----
    auto compute_stage = [&](int buf) {
        uint32_t sb = smem + buf * STAGE_BYTES;
        uint32_t a_h = sb, b_h = sb + MAT_BYTES;
#pragma unroll
        for (int ks = 0; ks < 4; ks++) {
            uint32_t ah[4][4], bh[4][4];
#pragma unroll
            for (int mt = 0; mt < 4; mt++) {
                int row = wm * 64 + mt * 16 + (lane & 15);
                int chk = ks * 2 + (lane >> 4);
                uint32_t off = row * 128 + ((chk ^ (row & 7)) << 4);
                LDSM4(ah[mt], a_h + off);
            }
#pragma unroll
            for (int bp = 0; bp < 4; bp++) {
                int row = wn * 64 + bp * 16 + (lane & 7) + ((lane >> 4) & 1) * 8;
                int chk = ks * 2 + ((lane >> 3) & 1);
                uint32_t off = row * 128 + ((chk ^ (row & 7)) << 4);
                LDSM4(bh[bp], b_h + off);
            }
            // 32 MMAs, all distinct accumulators -> no intra-ks dependency
#pragma unroll
            for (int mt = 0; mt < 4; mt++)
#pragma unroll
                for (int bp = 0; bp < 4; bp++) {
                    MMA16816(acc[mt][bp * 2 + 0], ah[mt], bh[bp][0], bh[bp][1]);
                    MMA16816(acc[mt][bp * 2 + 1], ah[mt], bh[bp][2], bh[bp][3]);
                }
        }
    };

    load_stage(0, 0); CP_COMMIT();
    load_stage(1, 1); CP_COMMIT();

    for (int s = 0; s < HSTEPS; s++) {
        if (s < HSTEPS - 1) { CP_WAIT(1); } else { CP_WAIT(0); }
        __syncthreads();            // stage s resident; buffer (s+2)%3 free
        if (s + 2 < HSTEPS) { load_stage(s + 2, (s + 2) % NSTAGE); CP_COMMIT(); }
        compute_stage(s % NSTAGE);  // overlaps with in-flight load
    }

    // ---- epilogue: add bias, exp ----
    int g = lane >> 2, tg = lane & 3;
#pragma unroll
    for (int bp = 0; bp < 8; bp++) {
        int col = c0 + wn * 64 + bp * 8 + tg * 2;
        float2 bn = *reinterpret_cast<const float2*>(g_bn + col);
        float2 pn = *reinterpret_cast<const float2*>(g_pn + col);
#pragma unroll
        for (int mt = 0; mt < 4; mt++) {
            int r0 = m0 + wm * 64 + mt * 16 + g;
            float2 e0, e1;
            e0.x = fexp(acc[mt][bp][0] + bn.x);
            e0.y = fexp(acc[mt][bp][1] + bn.y);
            e1.x = fexp(acc[mt][bp][2] + bn.x);
            e1.y = fexp(acc[mt][bp][3] + bn.y);
            *reinterpret_cast<float2*>(out_pmn + (size_t)r0 * Cdim + col) = e0;
            *reinterpret_cast<float2*>(out_pmn + (size_t)(r0 + 8) * Cdim + col) = e1;
            *reinterpret_cast<float2*>(out_pnn + (size_t)r0 * Cdim + col) = pn;
            *reinterpret_cast<float2*>(out_pnn + (size_t)(r0 + 8) * Cdim + col) = pn;
        }
    }
}

// ---------------- launch --------------------------------------------------------
extern "C" void kernel_launch(void* const* d_in, const int* in_sizes, int n_in,
                              void* d_out, int out_size) {
    const float* input  = (const float*)d_in[0];
    const float* weight = (const float*)d_in[1];
    const float* bias   = (const float*)d_in[2];
    const float* up     = (const float*)d_in[3];
    const int*   target = (const int*)d_in[4];
    const int*   noise  = (const int*)d_in[5];

    float* out     = (float*)d_out;
    float* out_pmt = out;
    float* out_pnt = out + Mdim;
    float* out_pmn = out + 2 * Mdim;
    float* out_pnn = out_pmn + (size_t)Mdim * Cdim;

    cudaFuncSetAttribute(nce_mma, cudaFuncAttributeMaxDynamicSharedMemorySize,
                         SMEM_TOTAL);

    split_a_kernel<<<Mdim, 256>>>(input);
    split_b_kernel<<<Cdim, 256>>>(weight, bias, up, noise);
    target_kernel<<<Mdim / 8, dim3(32, 8)>>>(input, weight, bias, up, target,
                                             out_pmt, out_pnt);
    nce_mma<<<(Mdim / BM) * (Cdim / BN), 128, SMEM_TOTAL>>>(out_pmn, out_pnn);
}

// round 8
// speedup vs baseline: 7.4534x; 1.0165x over previous
#include <cuda_runtime.h>
#include <cuda_bf16.h>
#include <cuda_fp16.h>
#include <cstdint>

#define Mdim 8192          // output rows  (problem N)
#define Cdim 4096          // output cols  (problem K, noise count)
#define Hdim 1024          // reduction dim

#define BM 128
#define BN 128
#define BH 64
#define HSTEPS (Hdim / BH)     // 16
#define NSTAGE 3
#define MAT_BYTES 16384        // 128 rows x 64 fp16 (128B rows)
#define STAGE_BYTES (2 * MAT_BYTES)        // Ah, Bh
#define SMEM_TOTAL (NSTAGE * STAGE_BYTES)  // 96 KB -> 2 CTAs/SM

// ---------------- static device scratch (no runtime alloc allowed) ----------
__device__ __align__(16) __half g_ah[(size_t)Mdim * Hdim];   // fp16(A)
__device__ __align__(16) __half g_bh[(size_t)Cdim * Hdim];   // fp16(Wn)
__device__ __align__(16) float g_bn[Cdim];
__device__ __align__(16) float g_pn[Cdim];

// ---------------- helpers ----------------------------------------------------
__device__ __forceinline__ uint32_t smem_u32(const void* p) {
    uint32_t a;
    asm("{ .reg .u64 t; cvta.to.shared.u64 t, %1; cvt.u32.u64 %0, t; }"
        : "=r"(a) : "l"(p));
    return a;
}

#define LDSM4(r, addr) \
    asm volatile("ldmatrix.sync.aligned.m8n8.x4.shared.b16 {%0,%1,%2,%3}, [%4];" \
                 : "=r"((r)[0]), "=r"((r)[1]), "=r"((r)[2]), "=r"((r)[3]) \
                 : "r"(addr))

#define MMA16816(d, a, b0, b1) \
    asm volatile("mma.sync.aligned.m16n8k16.row.col.f32.f16.f16.f32 " \
                 "{%0,%1,%2,%3}, {%4,%5,%6,%7}, {%8,%9}, {%0,%1,%2,%3};" \
                 : "+f"((d)[0]), "+f"((d)[1]), "+f"((d)[2]), "+f"((d)[3]) \
                 : "r"((a)[0]), "r"((a)[1]), "r"((a)[2]), "r"((a)[3]), \
                   "r"(b0), "r"(b1))

__device__ __forceinline__ void cp_async16(uint32_t dst, const void* src) {
    asm volatile("cp.async.cg.shared.global [%0], [%1], 16;"
                 :: "r"(dst), "l"(src) : "memory");
}
#define CP_COMMIT() asm volatile("cp.async.commit_group;" ::: "memory")
#define CP_WAIT(n)  asm volatile("cp.async.wait_group %0;" :: "n"(n) : "memory")

// FFMA-only exp (avoids MUFU throughput wall for 33.5M calls).
__device__ __forceinline__ float fexp(float x) {
    float t = x * 1.4426950408889634f;
    float r = rintf(t);
    float f = t - r;
    float p = 1.5403530393381608e-4f;
    p = fmaf(p, f, 1.3333558146428443e-3f);
    p = fmaf(p, f, 9.6181291076284771e-3f);
    p = fmaf(p, f, 5.5504108664821580e-2f);
    p = fmaf(p, f, 2.4022650695910072e-1f);
    p = fmaf(p, f, 6.9314718055994531e-1f);
    p = fmaf(p, f, 1.0f);
    int e = (int)r;
    return __int_as_float(__float_as_int(p) + (e << 23));
}

// ---------------- fused preprocessing -----------------------------------------
// blocks [0, Mdim)                : fp16-convert one A row
// blocks [Mdim, Mdim+Cdim)        : gather+fp16-convert one noise W row + bias/up
// blocks [Mdim+Cdim, +Mdim/8)     : pmt/pnt for 8 rows (one warp each)
__global__ void prep_kernel(const float* __restrict__ input,
                            const float* __restrict__ weight,
                            const float* __restrict__ bias,
                            const float* __restrict__ up,
                            const int* __restrict__ target,
                            const int* __restrict__ noise,
                            float* __restrict__ out_pmt,
                            float* __restrict__ out_pnt) {
    int b = blockIdx.x;
    int t = threadIdx.x;
    if (b < Mdim) {
        float4 v = reinterpret_cast<const float4*>(input + (size_t)b * Hdim)[t];
        __half2 p0 = __halves2half2(__float2half_rn(v.x), __float2half_rn(v.y));
        __half2 p1 = __halves2half2(__float2half_rn(v.z), __float2half_rn(v.w));
        uint2 u;
        u.x = reinterpret_cast<uint32_t&>(p0);
        u.y = reinterpret_cast<uint32_t&>(p1);
        reinterpret_cast<uint2*>(g_ah)[((size_t)b * Hdim) / 4 + t] = u;
    } else if (b < Mdim + Cdim) {
        int k = b - Mdim;
        int v = noise[k];
        float4 w = reinterpret_cast<const float4*>(weight + (size_t)v * Hdim)[t];
        __half2 p0 = __halves2half2(__float2half_rn(w.x), __float2half_rn(w.y));
        __half2 p1 = __halves2half2(__float2half_rn(w.z), __float2half_rn(w.w));
        uint2 u;
        u.x = reinterpret_cast<uint32_t&>(p0);
        u.y = reinterpret_cast<uint32_t&>(p1);
        reinterpret_cast<uint2*>(g_bh)[((size_t)k * Hdim) / 4 + t] = u;
        if (t == 0) { g_bn[k] = bias[v]; g_pn[k] = up[v]; }
    } else {
        int n = (b - Mdim - Cdim) * 8 + (t >> 5);
        int lane = t & 31;
        int tgt = target[n];
        const float4* a = reinterpret_cast<const float4*>(input + (size_t)n * Hdim);
        const float4* w = reinterpret_cast<const float4*>(weight + (size_t)tgt * Hdim);
        float s = 0.f;
#pragma unroll
        for (int j = 0; j < 8; j++) {
            float4 av = a[lane + j * 32];
            float4 wv = w[lane + j * 32];
            s += av.x * wv.x + av.y * wv.y + av.z * wv.z + av.w * wv.w;
        }
#pragma unroll
        for (int o = 16; o; o >>= 1) s += __shfl_xor_sync(0xffffffffu, s, o);
        if (lane == 0) {
            out_pmt[n] = expf(s + bias[tgt]);
            out_pnt[n] = up[tgt];
        }
    }
}

// ---------------- main mma.sync GEMM -------------------------------------------
// pmn[m,c] = fexp(sum_h Ah[m,h]*Bh[c,h] + bn[c]); pnn[m,c] = pn[c].
// 128x128 CTA tile, 4 warps of 64x64 (2x2 grid), 128 threads, BH=64,
// 3-stage pipeline, 2 CTAs/SM. A-LDSM interleaved with MMA groups.
__global__ __launch_bounds__(128, 2)
void nce_mma(float* __restrict__ out_pmn, float* __restrict__ out_pnn) {
    extern __shared__ uint8_t dynsm[];
    uint32_t smem = smem_u32(dynsm);

    const int tid = threadIdx.x;
    const int lane = tid & 31;
    const int wid = tid >> 5;
    const int wm = wid & 1;           // warp row 0..1  (64 rows each)
    const int wn = wid >> 1;          // warp col 0..1  (64 cols each)

    const int cid = blockIdx.x;
    const int tile_m = cid & 63;      // consecutive CTAs share tile_n -> B reuse
    const int tile_n = cid >> 6;
    const int m0 = tile_m * BM;
    const int c0 = tile_n * BN;

    float acc[4][8][4];
#pragma unroll
    for (int i = 0; i < 4; i++)
#pragma unroll
        for (int j = 0; j < 8; j++)
#pragma unroll
            for (int q = 0; q < 4; q++) acc[i][j][q] = 0.f;

    // ---- stage loader: 2 matrices x 128 rows x 8 chunks of 16B, 128 threads ----
    auto load_stage = [&](int s, int buf) {
        uint32_t sb = smem + buf * STAGE_BYTES;
        const uint8_t* gsrc[2] = {
            reinterpret_cast<const uint8_t*>(g_ah) + (size_t)m0 * 2048,
            reinterpret_cast<const uint8_t*>(g_bh) + (size_t)c0 * 2048 };
        int hbyte = s * 128;   // 64 fp16 = 128B per stage along H
#pragma unroll
        for (int mat = 0; mat < 2; mat++) {
            uint32_t mb = sb + mat * MAT_BYTES;
#pragma unroll
            for (int i = 0; i < 8; i++) {
                int ch = i * 128 + tid;       // 0..1023
                int row = ch >> 3;
                int kc = ch & 7;
                uint32_t dst = mb + row * 128 + ((kc ^ (row & 7)) << 4);
                cp_async16(dst, gsrc[mat] + (size_t)row * 2048 + hbyte + kc * 16);
            }
        }
    };

    // ---- per-stage compute: B burst, then A-LDSM interleaved with MMA groups ----
    auto compute_stage = [&](int buf) {
        uint32_t sb = smem + buf * STAGE_BYTES;
        uint32_t a_h = sb, b_h = sb + MAT_BYTES;
#pragma unroll
        for (int ks = 0; ks < 4; ks++) {
            uint32_t ah[4][4], bh[4][4];
#pragma unroll
            for (int bp = 0; bp < 4; bp++) {
                int row = wn * 64 + bp * 16 + (lane & 7) + ((lane >> 4) & 1) * 8;
                int chk = ks * 2 + ((lane >> 3) & 1);
                uint32_t off = row * 128 + ((chk ^ (row & 7)) << 4);
                LDSM4(bh[bp], b_h + off);
            }
            {   // first A group
                int row = wm * 64 + 0 * 16 + (lane & 15);
                int chk = ks * 2 + (lane >> 4);
                uint32_t off = row * 128 + ((chk ^ (row & 7)) << 4);
                LDSM4(ah[0], a_h + off);
            }
#pragma unroll
            for (int mt = 0; mt < 4; mt++) {
                if (mt < 3) {   // prefetch next A group; latency hides under 8 MMAs
                    int row = wm * 64 + (mt + 1) * 16 + (lane & 15);
                    int chk = ks * 2 + (lane >> 4);
                    uint32_t off = row * 128 + ((chk ^ (row & 7)) << 4);
                    LDSM4(ah[mt + 1], a_h + off);
                }
#pragma unroll
                for (int bp = 0; bp < 4; bp++) {
                    MMA16816(acc[mt][bp * 2 + 0], ah[mt], bh[bp][0], bh[bp][1]);
                    MMA16816(acc[mt][bp * 2 + 1], ah[mt], bh[bp][2], bh[bp][3]);
                }
            }
        }
    };

    load_stage(0, 0); CP_COMMIT();
    load_stage(1, 1); CP_COMMIT();

    for (int s = 0; s < HSTEPS; s++) {
        if (s < HSTEPS - 1) { CP_WAIT(1); } else { CP_WAIT(0); }
        __syncthreads();            // stage s resident; buffer (s+2)%3 free
        if (s + 2 < HSTEPS) { load_stage(s + 2, (s + 2) % NSTAGE); CP_COMMIT(); }
        compute_stage(s % NSTAGE);  // overlaps with in-flight load
    }

    // ---- epilogue: add bias, exp ----
    int g = lane >> 2, tg = lane & 3;
#pragma unroll
    for (int bp = 0; bp < 8; bp++) {
        int col = c0 + wn * 64 + bp * 8 + tg * 2;
        float2 bn = *reinterpret_cast<const float2*>(g_bn + col);
        float2 pn = *reinterpret_cast<const float2*>(g_pn + col);
#pragma unroll
        for (int mt = 0; mt < 4; mt++) {
            int r0 = m0 + wm * 64 + mt * 16 + g;
            float2 e0, e1;
            e0.x = fexp(acc[mt][bp][0] + bn.x);
            e0.y = fexp(acc[mt][bp][1] + bn.y);
            e1.x = fexp(acc[mt][bp][2] + bn.x);
            e1.y = fexp(acc[mt][bp][3] + bn.y);
            *reinterpret_cast<float2*>(out_pmn + (size_t)r0 * Cdim + col) = e0;
            *reinterpret_cast<float2*>(out_pmn + (size_t)(r0 + 8) * Cdim + col) = e1;
            *reinterpret_cast<float2*>(out_pnn + (size_t)r0 * Cdim + col) = pn;
            *reinterpret_cast<float2*>(out_pnn + (size_t)(r0 + 8) * Cdim + col) = pn;
        }
    }
}

// ---------------- launch --------------------------------------------------------
extern "C" void kernel_launch(void* const* d_in, const int* in_sizes, int n_in,
                              void* d_out, int out_size) {
    const float* input  = (const float*)d_in[0];
    const float* weight = (const float*)d_in[1];
    const float* bias   = (const float*)d_in[2];
    const float* up     = (const float*)d_in[3];
    const int*   target = (const int*)d_in[4];
    const int*   noise  = (const int*)d_in[5];

    float* out     = (float*)d_out;
    float* out_pmt = out;
    float* out_pnt = out + Mdim;
    float* out_pmn = out + 2 * Mdim;
    float* out_pnn = out_pmn + (size_t)Mdim * Cdim;

    cudaFuncSetAttribute(nce_mma, cudaFuncAttributeMaxDynamicSharedMemorySize,
                         SMEM_TOTAL);

    prep_kernel<<<Mdim + Cdim + Mdim / 8, 256>>>(input, weight, bias, up,
                                                 target, noise, out_pmt, out_pnt);
    nce_mma<<<(Mdim / BM) * (Cdim / BN), 128, SMEM_TOTAL>>>(out_pmn, out_pnn);
}

// round 9
// speedup vs baseline: 7.9157x; 1.0620x over previous
#include <cuda_runtime.h>
#include <cuda_bf16.h>
#include <cuda_fp16.h>
#include <cstdint>

#define Mdim 8192          // output rows  (problem N)
#define Cdim 4096          // output cols  (problem K, noise count)
#define Hdim 1024          // reduction dim

#define BM 128
#define BN 128
#define BH 64
#define HSTEPS (Hdim / BH)     // 16
#define NSTAGE 3
#define MAT_BYTES 16384        // 128 rows x 64 fp16 (128B rows), one tile
#define STAGE_BYTES (2 * MAT_BYTES)        // Ah, Bh
#define SMEM_TOTAL (NSTAGE * STAGE_BYTES)  // 96 KB -> 2 CTAs/SM

// ---------------- static device scratch (no runtime alloc allowed) ----------
// Tile-contiguous, pre-swizzled layout: tile (rowblk, s) of 128 rows x 64 cols
// fp16 lives at byte offset ((rowblk*HSTEPS + s) * MAT_BYTES), swizzled rows.
__device__ __align__(16) uint8_t g_ah[(size_t)Mdim * Hdim * 2];
__device__ __align__(16) uint8_t g_bh[(size_t)Cdim * Hdim * 2];
__device__ __align__(16) float g_bn[Cdim];
__device__ __align__(16) float g_pn[Cdim];

// ---------------- helpers ----------------------------------------------------
__device__ __forceinline__ uint32_t smem_u32(const void* p) {
    uint32_t a;
    asm("{ .reg .u64 t; cvta.to.shared.u64 t, %1; cvt.u32.u64 %0, t; }"
        : "=r"(a) : "l"(p));
    return a;
}

#define LDSM4(r, addr) \
    asm volatile("ldmatrix.sync.aligned.m8n8.x4.shared.b16 {%0,%1,%2,%3}, [%4];" \
                 : "=r"((r)[0]), "=r"((r)[1]), "=r"((r)[2]), "=r"((r)[3]) \
                 : "r"(addr))

#define MMA16816(d, a, b0, b1) \
    asm volatile("mma.sync.aligned.m16n8k16.row.col.f32.f16.f16.f32 " \
                 "{%0,%1,%2,%3}, {%4,%5,%6,%7}, {%8,%9}, {%0,%1,%2,%3};" \
                 : "+f"((d)[0]), "+f"((d)[1]), "+f"((d)[2]), "+f"((d)[3]) \
                 : "r"((a)[0]), "r"((a)[1]), "r"((a)[2]), "r"((a)[3]), \
                   "r"(b0), "r"(b1))

__device__ __forceinline__ void mbar_init(uint32_t m, uint32_t cnt) {
    asm volatile("mbarrier.init.shared.b64 [%0], %1;" :: "r"(m), "r"(cnt) : "memory");
}
__device__ __forceinline__ void mbar_expect_tx(uint32_t m, uint32_t bytes) {
    asm volatile("mbarrier.arrive.expect_tx.shared.b64 _, [%0], %1;"
                 :: "r"(m), "r"(bytes) : "memory");
}
__device__ __forceinline__ void mbar_arrive(uint32_t m) {
    asm volatile("mbarrier.arrive.shared.b64 _, [%0];" :: "r"(m) : "memory");
}
__device__ __forceinline__ void wait_parity(uint32_t m, uint32_t ph) {
    asm volatile(
        "{\n\t.reg .pred P;\n\t"
        "WLP_%=:\n\t"
        "mbarrier.try_wait.parity.acquire.cta.shared::cta.b64 P, [%0], %1, 0x989680;\n\t"
        "@P bra.uni WDP_%=;\n\t"
        "bra.uni WLP_%=;\n\t"
        "WDP_%=:\n\t}"
        :: "r"(m), "r"(ph) : "memory");
}
__device__ __forceinline__ void bulk_ld(uint32_t dst, const void* src,
                                        uint32_t bytes, uint32_t mbar) {
    asm volatile(
        "cp.async.bulk.shared::cluster.global.mbarrier::complete_tx::bytes "
        "[%0], [%1], %2, [%3];"
        :: "r"(dst), "l"(src), "r"(bytes), "r"(mbar) : "memory");
}

// FFMA-only exp (avoids MUFU throughput wall for 33.5M calls).
__device__ __forceinline__ float fexp(float x) {
    float t = x * 1.4426950408889634f;
    float r = rintf(t);
    float f = t - r;
    float p = 1.5403530393381608e-4f;
    p = fmaf(p, f, 1.3333558146428443e-3f);
    p = fmaf(p, f, 9.6181291076284771e-3f);
    p = fmaf(p, f, 5.5504108664821580e-2f);
    p = fmaf(p, f, 2.4022650695910072e-1f);
    p = fmaf(p, f, 6.9314718055994531e-1f);
    p = fmaf(p, f, 1.0f);
    int e = (int)r;
    return __int_as_float(__float_as_int(p) + (e << 23));
}

// tiled + swizzled store of 4 fp16 (8 bytes) for logical (rowblk, r, col4grp)
__device__ __forceinline__ void tile_store(uint8_t* base, int rowblk, int r,
                                           int t, uint2 u) {
    int h = t * 4;                 // starting col in [0,1024)
    int s = h >> 6;                // H-stage tile index
    int c = h & 63;                // col within tile
    size_t blk = ((size_t)(rowblk * HSTEPS + s)) * MAT_BYTES;
    int byte = c * 2;              // 0..127, 8B granularity
    int kc = byte >> 4;            // 16B chunk 0..7
    uint32_t off = (uint32_t)(r * 128 + ((kc ^ (r & 7)) << 4) + (byte & 15));
    *reinterpret_cast<uint2*>(base + blk + off) = u;
}

// ---------------- fused preprocessing -----------------------------------------
// blocks [0, Mdim)                : fp16-convert one A row into tiled layout
// blocks [Mdim, Mdim+Cdim)        : gather+convert one noise W row + bias/up
// blocks [Mdim+Cdim, +Mdim/8)     : pmt/pnt for 8 rows (one warp each)
__global__ void prep_kernel(const float* __restrict__ input,
                            const float* __restrict__ weight,
                            const float* __restrict__ bias,
                            const float* __restrict__ up,
                            const int* __restrict__ target,
                            const int* __restrict__ noise,
                            float* __restrict__ out_pmt,
                            float* __restrict__ out_pnt) {
    int b = blockIdx.x;
    int t = threadIdx.x;
    if (b < Mdim) {
        float4 v = reinterpret_cast<const float4*>(input + (size_t)b * Hdim)[t];
        __half2 p0 = __halves2half2(__float2half_rn(v.x), __float2half_rn(v.y));
        __half2 p1 = __halves2half2(__float2half_rn(v.z), __float2half_rn(v.w));
        uint2 u;
        u.x = reinterpret_cast<uint32_t&>(p0);
        u.y = reinterpret_cast<uint32_t&>(p1);
        tile_store(g_ah, b >> 7, b & 127, t, u);
    } else if (b < Mdim + Cdim) {
        int k = b - Mdim;
        int v = noise[k];
        float4 w = reinterpret_cast<const float4*>(weight + (size_t)v * Hdim)[t];
        __half2 p0 = __halves2half2(__float2half_rn(w.x), __float2half_rn(w.y));
        __half2 p1 = __halves2half2(__float2half_rn(w.z), __float2half_rn(w.w));
        uint2 u;
        u.x = reinterpret_cast<uint32_t&>(p0);
        u.y = reinterpret_cast<uint32_t&>(p1);
        tile_store(g_bh, k >> 7, k & 127, t, u);
        if (t == 0) { g_bn[k] = bias[v]; g_pn[k] = up[v]; }
    } else {
        int n = (b - Mdim - Cdim) * 8 + (t >> 5);
        int lane = t & 31;
        int tgt = target[n];
        const float4* a = reinterpret_cast<const float4*>(input + (size_t)n * Hdim);
        const float4* w = reinterpret_cast<const float4*>(weight + (size_t)tgt * Hdim);
        float s = 0.f;
#pragma unroll
        for (int j = 0; j < 8; j++) {
            float4 av = a[lane + j * 32];
            float4 wv = w[lane + j * 32];
            s += av.x * wv.x + av.y * wv.y + av.z * wv.z + av.w * wv.w;
        }
#pragma unroll
        for (int o = 16; o; o >>= 1) s += __shfl_xor_sync(0xffffffffu, s, o);
        if (lane == 0) {
            out_pmt[n] = expf(s + bias[tgt]);
            out_pnt[n] = up[tgt];
        }
    }
}

// ---------------- main mma.sync GEMM -------------------------------------------
// pmn[m,c] = fexp(sum_h Ah[m,h]*Bh[c,h] + bn[c]); pnn[m,c] = pn[c].
// 128x128 CTA tile, 4 warps of 64x64, mbarrier + cp.async.bulk pipeline,
// NO CTA-wide barrier in the mainloop. 3 stages, 2 CTAs/SM.
__global__ __launch_bounds__(128, 2)
void nce_mma(float* __restrict__ out_pmn, float* __restrict__ out_pnn) {
    extern __shared__ uint8_t dynsm[];
    __shared__ __align__(8) uint64_t barsto[2 * NSTAGE];
    uint32_t smem = smem_u32(dynsm);
    uint32_t bars = smem_u32(barsto);   // full[s]=bars+8s, empty[s]=bars+24+8s

    const int tid = threadIdx.x;
    const int lane = tid & 31;
    const int wid = tid >> 5;
    const int wm = wid & 1;           // warp row 0..1  (64 rows each)
    const int wn = wid >> 1;          // warp col 0..1  (64 cols each)

    const int cid = blockIdx.x;
    const int tile_m = cid & 63;      // consecutive CTAs share tile_n -> B reuse
    const int tile_n = cid >> 6;
    const int m0 = tile_m * BM;
    const int c0 = tile_n * BN;

    if (tid == 0) {
#pragma unroll
        for (int s = 0; s < NSTAGE; s++) {
            mbar_init(bars + 8 * s, 1);                // full: tx-based
            mbar_init(bars + 24 + 8 * s, 4);           // empty: 4 warp arrivals
        }
    }
    __syncthreads();
    if (lane == 0) {   // every warp frees all buffers once
#pragma unroll
        for (int s = 0; s < NSTAGE; s++) mbar_arrive(bars + 24 + 8 * s);
    }

    // producer priming: stages 0..2 (empty phase 0 completes via arrivals above)
    if (tid == 0) {
#pragma unroll
        for (int p = 0; p < NSTAGE; p++) {
            wait_parity(bars + 24 + 8 * p, 0);
            uint32_t fb = bars + 8 * p;
            mbar_expect_tx(fb, STAGE_BYTES);
            uint32_t dst = smem + p * STAGE_BYTES;
            bulk_ld(dst, g_ah + ((size_t)(tile_m * HSTEPS + p)) * MAT_BYTES,
                    MAT_BYTES, fb);
            bulk_ld(dst + MAT_BYTES,
                    g_bh + ((size_t)(tile_n * HSTEPS + p)) * MAT_BYTES,
                    MAT_BYTES, fb);
        }
    }

    float acc[4][8][4];
#pragma unroll
    for (int i = 0; i < 4; i++)
#pragma unroll
        for (int j = 0; j < 8; j++)
#pragma unroll
            for (int q = 0; q < 4; q++) acc[i][j][q] = 0.f;

    int ph_f = 0;          // full-parity, flips when buffer wraps
    int ph_e = 1;          // producer's in-loop empty parity (priming used 0)

    for (int s = 0; s < HSTEPS; s++) {
        int buf = s % NSTAGE;
        // consumer: wait stage resident
        wait_parity(bars + 8 * buf, (uint32_t)ph_f);
        if (buf == NSTAGE - 1) ph_f ^= 1;

        // ---- compute stage: warp tile 64x64, B burst + interleaved A LDSM ----
        uint32_t sb = smem + buf * STAGE_BYTES;
        uint32_t a_h = sb, b_h = sb + MAT_BYTES;
#pragma unroll
        for (int ks = 0; ks < 4; ks++) {
            uint32_t ah[4][4], bh[4][4];
#pragma unroll
            for (int bp = 0; bp < 4; bp++) {
                int row = wn * 64 + bp * 16 + (lane & 7) + ((lane >> 4) & 1) * 8;
                int chk = ks * 2 + ((lane >> 3) & 1);
                uint32_t off = row * 128 + ((chk ^ (row & 7)) << 4);
                LDSM4(bh[bp], b_h + off);
            }
            {
                int row = wm * 64 + (lane & 15);
                int chk = ks * 2 + (lane >> 4);
                uint32_t off = row * 128 + ((chk ^ (row & 7)) << 4);
                LDSM4(ah[0], a_h + off);
            }
#pragma unroll
            for (int mt = 0; mt < 4; mt++) {
                if (mt < 3) {
                    int row = wm * 64 + (mt + 1) * 16 + (lane & 15);
                    int chk = ks * 2 + (lane >> 4);
                    uint32_t off = row * 128 + ((chk ^ (row & 7)) << 4);
                    LDSM4(ah[mt + 1], a_h + off);
                }
#pragma unroll
                for (int bp = 0; bp < 4; bp++) {
                    MMA16816(acc[mt][bp * 2 + 0], ah[mt], bh[bp][0], bh[bp][1]);
                    MMA16816(acc[mt][bp * 2 + 1], ah[mt], bh[bp][2], bh[bp][3]);
                }
            }
        }

        // consumer: free the buffer
        if (lane == 0) mbar_arrive(bars + 24 + 8 * buf);

        // producer: refill this buffer with stage s+3 once all warps freed it
        if (tid == 0 && s + NSTAGE < HSTEPS) {
            wait_parity(bars + 24 + 8 * buf, (uint32_t)ph_e);
            if (buf == NSTAGE - 1) ph_e ^= 1;
            int p = s + NSTAGE;
            uint32_t fb = bars + 8 * buf;
            mbar_expect_tx(fb, STAGE_BYTES);
            uint32_t dst = smem + buf * STAGE_BYTES;
            bulk_ld(dst, g_ah + ((size_t)(tile_m * HSTEPS + p)) * MAT_BYTES,
                    MAT_BYTES, fb);
            bulk_ld(dst + MAT_BYTES,
                    g_bh + ((size_t)(tile_n * HSTEPS + p)) * MAT_BYTES,
                    MAT_BYTES, fb);
        }
    }

    // ---- epilogue: add bias, exp ----
    int g = lane >> 2, tg = lane & 3;
#pragma unroll
    for (int bp = 0; bp < 8; bp++) {
        int col = c0 + wn * 64 + bp * 8 + tg * 2;
        float2 bn = *reinterpret_cast<const float2*>(g_bn + col);
        float2 pn = *reinterpret_cast<const float2*>(g_pn + col);
#pragma unroll
        for (int mt = 0; mt < 4; mt++) {
            int r0 = m0 + wm * 64 + mt * 16 + g;
            float2 e0, e1;
            e0.x = fexp(acc[mt][bp][0] + bn.x);
            e0.y = fexp(acc[mt][bp][1] + bn.y);
            e1.x = fexp(acc[mt][bp][2] + bn.x);
            e1.y = fexp(acc[mt][bp][3] + bn.y);
            *reinterpret_cast<float2*>(out_pmn + (size_t)r0 * Cdim + col) = e0;
            *reinterpret_cast<float2*>(out_pmn + (size_t)(r0 + 8) * Cdim + col) = e1;
            *reinterpret_cast<float2*>(out_pnn + (size_t)r0 * Cdim + col) = pn;
            *reinterpret_cast<float2*>(out_pnn + (size_t)(r0 + 8) * Cdim + col) = pn;
        }
    }
}

// ---------------- launch --------------------------------------------------------
extern "C" void kernel_launch(void* const* d_in, const int* in_sizes, int n_in,
                              void* d_out, int out_size) {
    const float* input  = (const float*)d_in[0];
    const float* weight = (const float*)d_in[1];
    const float* bias   = (const float*)d_in[2];
    const float* up     = (const float*)d_in[3];
    const int*   target = (const int*)d_in[4];
    const int*   noise  = (const int*)d_in[5];

    float* out     = (float*)d_out;
    float* out_pmt = out;
    float* out_pnt = out + Mdim;
    float* out_pmn = out + 2 * Mdim;
    float* out_pnn = out_pmn + (size_t)Mdim * Cdim;

    cudaFuncSetAttribute(nce_mma, cudaFuncAttributeMaxDynamicSharedMemorySize,
                         SMEM_TOTAL);

    prep_kernel<<<Mdim + Cdim + Mdim / 8, 256>>>(input, weight, bias, up,
                                                 target, noise, out_pmt, out_pnt);
    nce_mma<<<(Mdim / BM) * (Cdim / BN), 128, SMEM_TOTAL>>>(out_pmn, out_pnn);
}

// round 10
// speedup vs baseline: 8.0019x; 1.0109x over previous
#include <cuda_runtime.h>
#include <cuda_bf16.h>
#include <cuda_fp16.h>
#include <cstdint>

#define Mdim 8192          // output rows  (problem N)
#define Cdim 4096          // output cols  (problem K, noise count)
#define Hdim 1024          // reduction dim

#define BM 128
#define BN 128
#define BH 64
#define HSTEPS (Hdim / BH)     // 16
#define NSTAGE 3
#define MAT_BYTES 16384        // 128 rows x 64 fp16 (128B rows), one tile
#define STAGE_BYTES (2 * MAT_BYTES)        // Ah, Bh
#define SMEM_TOTAL (NSTAGE * STAGE_BYTES)  // 96 KB -> 2 CTAs/SM

// ---------------- static device scratch (no runtime alloc allowed) ----------
// Tile-contiguous, pre-swizzled: tile (rowblk, s) of 128 rows x 64 fp16 cols
// at byte offset ((rowblk*HSTEPS + s) * MAT_BYTES), swizzled 128B rows.
__device__ __align__(16) uint8_t g_ah[(size_t)Mdim * Hdim * 2];
__device__ __align__(16) uint8_t g_bh[(size_t)Cdim * Hdim * 2];
__device__ __align__(16) float g_bn[Cdim];
__device__ __align__(16) float g_pn[Cdim];

// ---------------- helpers ----------------------------------------------------
__device__ __forceinline__ uint32_t smem_u32(const void* p) {
    uint32_t a;
    asm("{ .reg .u64 t; cvta.to.shared.u64 t, %1; cvt.u32.u64 %0, t; }"
        : "=r"(a) : "l"(p));
    return a;
}

#define LDSM4(r, addr) \
    asm volatile("ldmatrix.sync.aligned.m8n8.x4.shared.b16 {%0,%1,%2,%3}, [%4];" \
                 : "=r"((r)[0]), "=r"((r)[1]), "=r"((r)[2]), "=r"((r)[3]) \
                 : "r"(addr))

#define MMA16816(d, a, b0, b1) \
    asm volatile("mma.sync.aligned.m16n8k16.row.col.f32.f16.f16.f32 " \
                 "{%0,%1,%2,%3}, {%4,%5,%6,%7}, {%8,%9}, {%0,%1,%2,%3};" \
                 : "+f"((d)[0]), "+f"((d)[1]), "+f"((d)[2]), "+f"((d)[3]) \
                 : "r"((a)[0]), "r"((a)[1]), "r"((a)[2]), "r"((a)[3]), \
                   "r"(b0), "r"(b1))

__device__ __forceinline__ void mbar_init(uint32_t m, uint32_t cnt) {
    asm volatile("mbarrier.init.shared.b64 [%0], %1;" :: "r"(m), "r"(cnt) : "memory");
}
__device__ __forceinline__ void mbar_expect_tx(uint32_t m, uint32_t bytes) {
    asm volatile("mbarrier.arrive.expect_tx.shared.b64 _, [%0], %1;"
                 :: "r"(m), "r"(bytes) : "memory");
}
__device__ __forceinline__ void mbar_arrive(uint32_t m) {
    asm volatile("mbarrier.arrive.shared.b64 _, [%0];" :: "r"(m) : "memory");
}
__device__ __forceinline__ void wait_parity(uint32_t m, uint32_t ph) {
    asm volatile(
        "{\n\t.reg .pred P;\n\t"
        "WLP_%=:\n\t"
        "mbarrier.try_wait.parity.acquire.cta.shared::cta.b64 P, [%0], %1, 0x989680;\n\t"
        "@P bra.uni WDP_%=;\n\t"
        "bra.uni WLP_%=;\n\t"
        "WDP_%=:\n\t}"
        :: "r"(m), "r"(ph) : "memory");
}
__device__ __forceinline__ void bulk_ld(uint32_t dst, const void* src,
                                        uint32_t bytes, uint32_t mbar) {
    asm volatile(
        "cp.async.bulk.shared::cluster.global.mbarrier::complete_tx::bytes "
        "[%0], [%1], %2, [%3];"
        :: "r"(dst), "l"(src), "r"(bytes), "r"(mbar) : "memory");
}

// FFMA-only exp (avoids MUFU throughput wall for 33.5M calls).
__device__ __forceinline__ float fexp(float x) {
    float t = x * 1.4426950408889634f;
    float r = rintf(t);
    float f = t - r;
    float p = 1.5403530393381608e-4f;
    p = fmaf(p, f, 1.3333558146428443e-3f);
    p = fmaf(p, f, 9.6181291076284771e-3f);
    p = fmaf(p, f, 5.5504108664821580e-2f);
    p = fmaf(p, f, 2.4022650695910072e-1f);
    p = fmaf(p, f, 6.9314718055994531e-1f);
    p = fmaf(p, f, 1.0f);
    int e = (int)r;
    return __int_as_float(__float_as_int(p) + (e << 23));
}

// tiled + swizzled store of 4 fp16 (8 bytes) for logical (rowblk, r, col4grp)
__device__ __forceinline__ void tile_store(uint8_t* base, int rowblk, int r,
                                           int t, uint2 u) {
    int h = t * 4;                 // starting col in [0,1024)
    int s = h >> 6;                // H-stage tile index
    int c = h & 63;                // col within tile
    size_t blk = ((size_t)(rowblk * HSTEPS + s)) * MAT_BYTES;
    int byte = c * 2;              // 0..127, 8B granularity
    int kc = byte >> 4;            // 16B chunk 0..7
    uint32_t off = (uint32_t)(r * 128 + ((kc ^ (r & 7)) << 4) + (byte & 15));
    *reinterpret_cast<uint2*>(base + blk + off) = u;
}

// ---------------- fused preprocessing -----------------------------------------
__global__ void prep_kernel(const float* __restrict__ input,
                            const float* __restrict__ weight,
                            const float* __restrict__ bias,
                            const float* __restrict__ up,
                            const int* __restrict__ target,
                            const int* __restrict__ noise,
                            float* __restrict__ out_pmt,
                            float* __restrict__ out_pnt) {
    int b = blockIdx.x;
    int t = threadIdx.x;
    if (b < Mdim) {
        float4 v = reinterpret_cast<const float4*>(input + (size_t)b * Hdim)[t];
        __half2 p0 = __halves2half2(__float2half_rn(v.x), __float2half_rn(v.y));
        __half2 p1 = __halves2half2(__float2half_rn(v.z), __float2half_rn(v.w));
        uint2 u;
        u.x = reinterpret_cast<uint32_t&>(p0);
        u.y = reinterpret_cast<uint32_t&>(p1);
        tile_store(g_ah, b >> 7, b & 127, t, u);
    } else if (b < Mdim + Cdim) {
        int k = b - Mdim;
        int v = noise[k];
        float4 w = reinterpret_cast<const float4*>(weight + (size_t)v * Hdim)[t];
        __half2 p0 = __halves2half2(__float2half_rn(w.x), __float2half_rn(w.y));
        __half2 p1 = __halves2half2(__float2half_rn(w.z), __float2half_rn(w.w));
        uint2 u;
        u.x = reinterpret_cast<uint32_t&>(p0);
        u.y = reinterpret_cast<uint32_t&>(p1);
        tile_store(g_bh, k >> 7, k & 127, t, u);
        if (t == 0) { g_bn[k] = bias[v]; g_pn[k] = up[v]; }
    } else {
        int n = (b - Mdim - Cdim) * 8 + (t >> 5);
        int lane = t & 31;
        int tgt = target[n];
        const float4* a = reinterpret_cast<const float4*>(input + (size_t)n * Hdim);
        const float4* w = reinterpret_cast<const float4*>(weight + (size_t)tgt * Hdim);
        float s = 0.f;
#pragma unroll
        for (int j = 0; j < 8; j++) {
            float4 av = a[lane + j * 32];
            float4 wv = w[lane + j * 32];
            s += av.x * wv.x + av.y * wv.y + av.z * wv.z + av.w * wv.w;
        }
#pragma unroll
        for (int o = 16; o; o >>= 1) s += __shfl_xor_sync(0xffffffffu, s, o);
        if (lane == 0) {
            out_pmt[n] = expf(s + bias[tgt]);
            out_pnt[n] = up[tgt];
        }
    }
}

// ---------------- main mma.sync GEMM -------------------------------------------
// pmn[m,c] = fexp(sum_h Ah[m,h]*Bh[c,h] + bn[c]); pnn[m,c] = pn[c].
// 128x128 CTA tile, 4 warps of 64x64, mbarrier + cp.async.bulk pipeline,
// fragments double-buffered across ks (2 prefetch LDSM per 8-MMA group).
__global__ __launch_bounds__(128, 2)
void nce_mma(float* __restrict__ out_pmn, float* __restrict__ out_pnn) {
    extern __shared__ uint8_t dynsm[];
    __shared__ __align__(8) uint64_t barsto[2 * NSTAGE];
    uint32_t smem = smem_u32(dynsm);
    uint32_t bars = smem_u32(barsto);   // full[s]=bars+8s, empty[s]=bars+24+8s

    const int tid = threadIdx.x;
    const int lane = tid & 31;
    const int wid = tid >> 5;
    const int wm = wid & 1;           // warp row 0..1  (64 rows each)
    const int wn = wid >> 1;          // warp col 0..1  (64 cols each)

    const int cid = blockIdx.x;
    const int tile_m = cid & 63;      // consecutive CTAs share tile_n -> B reuse
    const int tile_n = cid >> 6;
    const int m0 = tile_m * BM;
    const int c0 = tile_n * BN;

    // per-lane LDSM row components (ks-independent)
    const int arow = wm * 64 + (lane & 15);
    const int achk0 = lane >> 4;
    const int brow = wn * 64 + (lane & 7) + ((lane >> 4) & 1) * 8;
    const int bchk0 = (lane >> 3) & 1;

    if (tid == 0) {
#pragma unroll
        for (int s = 0; s < NSTAGE; s++) {
            mbar_init(bars + 8 * s, 1);                // full: tx-based
            mbar_init(bars + 24 + 8 * s, 4);           // empty: 4 warp arrivals
        }
    }
    __syncthreads();
    if (lane == 0) {
#pragma unroll
        for (int s = 0; s < NSTAGE; s++) mbar_arrive(bars + 24 + 8 * s);
    }

    if (tid == 0) {   // producer priming
#pragma unroll
        for (int p = 0; p < NSTAGE; p++) {
            wait_parity(bars + 24 + 8 * p, 0);
            uint32_t fb = bars + 8 * p;
            mbar_expect_tx(fb, STAGE_BYTES);
            uint32_t dst = smem + p * STAGE_BYTES;
            bulk_ld(dst, g_ah + ((size_t)(tile_m * HSTEPS + p)) * MAT_BYTES,
                    MAT_BYTES, fb);
            bulk_ld(dst + MAT_BYTES,
                    g_bh + ((size_t)(tile_n * HSTEPS + p)) * MAT_BYTES,
                    MAT_BYTES, fb);
        }
    }

    float acc[4][8][4];
#pragma unroll
    for (int i = 0; i < 4; i++)
#pragma unroll
        for (int j = 0; j < 8; j++)
#pragma unroll
            for (int q = 0; q < 4; q++) acc[i][j][q] = 0.f;

    int ph_f = 0;
    int ph_e = 1;

    for (int s = 0; s < HSTEPS; s++) {
        int buf = s % NSTAGE;
        wait_parity(bars + 8 * buf, (uint32_t)ph_f);
        if (buf == NSTAGE - 1) ph_f ^= 1;

        uint32_t sb = smem + buf * STAGE_BYTES;
        uint32_t a_h = sb, b_h = sb + MAT_BYTES;

        // fragment ping-pong buffers across ks
        uint32_t ah[2][4][4], bh[2][4][4];

        // stage preamble: load all ks=0 fragments (one exposed burst per stage)
#pragma unroll
        for (int mt = 0; mt < 4; mt++) {
            int row = arow + mt * 16;
            uint32_t off = row * 128 + ((achk0 ^ (row & 7)) << 4);
            LDSM4(ah[0][mt], a_h + off);
        }
#pragma unroll
        for (int bp = 0; bp < 4; bp++) {
            int row = brow + bp * 16;
            uint32_t off = row * 128 + (((2 * 0 + bchk0) ^ (row & 7)) << 4);
            LDSM4(bh[0][bp], b_h + off);
        }

#pragma unroll
        for (int ks = 0; ks < 4; ks++) {
            int cur = ks & 1;
#pragma unroll
            for (int mt = 0; mt < 4; mt++) {
                if (ks < 3) {   // prefetch ks+1 fragments: 2 LDSM per 8 MMAs
                    int nchkA = (ks + 1) * 2 + achk0;
                    int rowA = arow + mt * 16;
                    uint32_t offA = rowA * 128 + ((nchkA ^ (rowA & 7)) << 4);
                    LDSM4(ah[cur ^ 1][mt], a_h + offA);
                    int nchkB = (ks + 1) * 2 + bchk0;
                    int rowB = brow + mt * 16;
                    uint32_t offB = rowB * 128 + ((nchkB ^ (rowB & 7)) << 4);
                    LDSM4(bh[cur ^ 1][mt], b_h + offB);
                }
#pragma unroll
                for (int bp = 0; bp < 4; bp++) {
                    MMA16816(acc[mt][bp * 2 + 0], ah[cur][mt],
                             bh[cur][bp][0], bh[cur][bp][1]);
                    MMA16816(acc[mt][bp * 2 + 1], ah[cur][mt],
                             bh[cur][bp][2], bh[cur][bp][3]);
                }
            }
        }

        if (lane == 0) mbar_arrive(bars + 24 + 8 * buf);

        if (tid == 0 && s + NSTAGE < HSTEPS) {
            wait_parity(bars + 24 + 8 * buf, (uint32_t)ph_e);
            if (buf == NSTAGE - 1) ph_e ^= 1;
            int p = s + NSTAGE;
            uint32_t fb = bars + 8 * buf;
            mbar_expect_tx(fb, STAGE_BYTES);
            uint32_t dst = smem + buf * STAGE_BYTES;
            bulk_ld(dst, g_ah + ((size_t)(tile_m * HSTEPS + p)) * MAT_BYTES,
                    MAT_BYTES, fb);
            bulk_ld(dst + MAT_BYTES,
                    g_bh + ((size_t)(tile_n * HSTEPS + p)) * MAT_BYTES,
                    MAT_BYTES, fb);
        }
    }

    // ---- epilogue: add bias, exp ----
    int g = lane >> 2, tg = lane & 3;
#pragma unroll
    for (int bp = 0; bp < 8; bp++) {
        int col = c0 + wn * 64 + bp * 8 + tg * 2;
        float2 bn = *reinterpret_cast<const float2*>(g_bn + col);
        float2 pn = *reinterpret_cast<const float2*>(g_pn + col);
#pragma unroll
        for (int mt = 0; mt < 4; mt++) {
            int r0 = m0 + wm * 64 + mt * 16 + g;
            float2 e0, e1;
            e0.x = fexp(acc[mt][bp][0] + bn.x);
            e0.y = fexp(acc[mt][bp][1] + bn.y);
            e1.x = fexp(acc[mt][bp][2] + bn.x);
            e1.y = fexp(acc[mt][bp][3] + bn.y);
            *reinterpret_cast<float2*>(out_pmn + (size_t)r0 * Cdim + col) = e0;
            *reinterpret_cast<float2*>(out_pmn + (size_t)(r0 + 8) * Cdim + col) = e1;
            *reinterpret_cast<float2*>(out_pnn + (size_t)r0 * Cdim + col) = pn;
            *reinterpret_cast<float2*>(out_pnn + (size_t)(r0 + 8) * Cdim + col) = pn;
        }
    }
}

// ---------------- launch --------------------------------------------------------
extern "C" void kernel_launch(void* const* d_in, const int* in_sizes, int n_in,
                              void* d_out, int out_size) {
    const float* input  = (const float*)d_in[0];
    const float* weight = (const float*)d_in[1];
    const float* bias   = (const float*)d_in[2];
    const float* up     = (const float*)d_in[3];
    const int*   target = (const int*)d_in[4];
    const int*   noise  = (const int*)d_in[5];

    float* out     = (float*)d_out;
    float* out_pmt = out;
    float* out_pnt = out + Mdim;
    float* out_pmn = out + 2 * Mdim;
    float* out_pnn = out_pmn + (size_t)Mdim * Cdim;

    cudaFuncSetAttribute(nce_mma, cudaFuncAttributeMaxDynamicSharedMemorySize,
                         SMEM_TOTAL);

    prep_kernel<<<Mdim + Cdim + Mdim / 8, 256>>>(input, weight, bias, up,
                                                 target, noise, out_pmt, out_pnt);
    nce_mma<<<(Mdim / BM) * (Cdim / BN), 128, SMEM_TOTAL>>>(out_pmn, out_pnn);
}